// round 2
// baseline (speedup 1.0000x reference)
#include <cuda_runtime.h>
#include <math.h>

#define Bq 64
#define TSq 300
#define TDq 180
#define Fq 128
#define Hq 512
#define Lq 4
#define Gq 2048   // 4*H
#define NBPD 64   // blocks per direction in persistent LSTM

// ---------------- static device scratch (no runtime allocation) ----------------
__device__ float g_xp[(size_t)2 * Bq * TSq * Gq];      // input projections (2 dirs worst case)
__device__ float g_X0[(size_t)Bq * TSq * 1024];        // layer activation ping
__device__ float g_X1[(size_t)Bq * TSq * 1024];        // layer activation pong
__device__ float g_dcat[(size_t)Bq * TDq * 640];       // decoder concat input
__device__ float g_hwork[2][2 * Bq * Hq];              // h ping-pong (2 dirs)
__device__ float g_cwork[2 * Bq * Hq];                 // c state (2 dirs)
__device__ float g_hs[Lq * Bq * 1024];                 // stacked encoder final h (fw|bw)
__device__ float g_cs[Lq * Bq * 1024];                 // stacked encoder final c
__device__ float g_h0[Lq * Bq * Hq];                   // decoder initial h per layer
__device__ float g_c0[Lq * Bq * Hq];                   // decoder initial c per layer
__device__ unsigned g_barCnt;                          // grid barrier (zero-init)
__device__ unsigned g_barGen;

// ---------------------------------------------------------------------------
// software grid barrier (all blocks co-resident by construction)
// ---------------------------------------------------------------------------
__device__ __forceinline__ void gridBarrier()
{
    __syncthreads();
    if (threadIdx.x == 0) {
        const unsigned gen = *((volatile unsigned*)&g_barGen);
        __threadfence();                       // release all prior writes
        if (atomicAdd(&g_barCnt, 1u) == gridDim.x - 1u) {
            atomicExch(&g_barCnt, 0u);
            __threadfence();
            atomicAdd(&g_barGen, 1u);
        } else {
            while (*((volatile unsigned*)&g_barGen) == gen) { __nanosleep(64); }
        }
        __threadfence();                       // acquire
    }
    __syncthreads();
}

// ---------------------------------------------------------------------------
// Generic tiled fp32 GEMM: C[M,N] = A[M,K] @ W[N,K]^T + bias[N]  (opt tanh)
// BM=BN=128, BK=8, 256 threads, 8x8 micro-tile. M%128==0, N%128==0, K%8==0.
// blockIdx.z indexes independent weight sets (encoder directions).
// ---------------------------------------------------------------------------
__global__ __launch_bounds__(256)
void gemm128(const float* __restrict__ A, const float* __restrict__ W,
             const float* __restrict__ bias, float* __restrict__ C,
             int M, int N, int K,
             size_t aZ, size_t wZ, size_t bZ, size_t cZ, int act)
{
    A    += blockIdx.z * aZ;
    W    += blockIdx.z * wZ;
    bias += blockIdx.z * bZ;
    C    += blockIdx.z * cZ;
    const int n0 = blockIdx.x * 128;
    const int m0 = blockIdx.y * 128;

    __shared__ float As[8][128];
    __shared__ float Bs[8][128];

    const int tid = threadIdx.x;
    const int ty = tid >> 4, tx = tid & 15;
    const int lrow = tid >> 1;
    const int lq   = (tid & 1) * 4;

    float acc[8][8];
#pragma unroll
    for (int i = 0; i < 8; i++)
#pragma unroll
        for (int j = 0; j < 8; j++) acc[i][j] = 0.f;

    for (int k0 = 0; k0 < K; k0 += 8) {
        float4 av = *(const float4*)(A + (size_t)(m0 + lrow) * K + k0 + lq);
        float4 wv = *(const float4*)(W + (size_t)(n0 + lrow) * K + k0 + lq);
        As[lq + 0][lrow] = av.x; As[lq + 1][lrow] = av.y;
        As[lq + 2][lrow] = av.z; As[lq + 3][lrow] = av.w;
        Bs[lq + 0][lrow] = wv.x; Bs[lq + 1][lrow] = wv.y;
        Bs[lq + 2][lrow] = wv.z; Bs[lq + 3][lrow] = wv.w;
        __syncthreads();
#pragma unroll
        for (int k = 0; k < 8; k++) {
            float a[8], b[8];
            *(float4*)&a[0] = *(const float4*)&As[k][ty * 8];
            *(float4*)&a[4] = *(const float4*)&As[k][ty * 8 + 4];
            *(float4*)&b[0] = *(const float4*)&Bs[k][tx * 8];
            *(float4*)&b[4] = *(const float4*)&Bs[k][tx * 8 + 4];
#pragma unroll
            for (int i = 0; i < 8; i++)
#pragma unroll
                for (int j = 0; j < 8; j++)
                    acc[i][j] += a[i] * b[j];
        }
        __syncthreads();
    }

#pragma unroll
    for (int i = 0; i < 8; i++) {
        const size_t m = (size_t)(m0 + ty * 8 + i);
#pragma unroll
        for (int j = 0; j < 8; j++) {
            const int n = n0 + tx * 8 + j;
            float v = acc[i][j] + bias[n];
            if (act) v = tanhf(v);
            C[m * N + n] = v;
        }
    }
}

// ---------------------------------------------------------------------------
// Persistent LSTM layer. Grid = dirs*NBPD blocks, 256 threads.
// Each block owns 8 hidden units (32 gate cols) x all 64 batch rows of one
// direction. Whh tile (32 cols x 512 K) preloaded once into smem. Loops over
// all T steps with a software grid barrier between steps.
// smem: Ws[512][34] | Hs[32][68] | Gs[64][33]
// ---------------------------------------------------------------------------
#define WS_S 34
#define HS_S 68
#define GS_S 33
#define SMEM_FLOATS (512 * WS_S + 32 * HS_S + 64 * GS_S)

__global__ __launch_bounds__(256)
void lstm_persist(const float* __restrict__ xp, const float* __restrict__ Whh,
                  const float* __restrict__ h0, const float* __restrict__ c0,
                  float* __restrict__ hA, float* __restrict__ hB,
                  float* __restrict__ cSt, float* __restrict__ y,
                  float* __restrict__ hFin, float* __restrict__ cFin,
                  int T, int revDir1, int yStride, int yDirMult)
{
    extern __shared__ float sm[];
    float* Ws = sm;                       // [512][34]
    float* Hs = sm + 512 * WS_S;          // [32][68]
    float* Gs = Hs + 32 * HS_S;           // [64][33]

    const int tid = threadIdx.x;
    const int ty = tid >> 4, tx = tid & 15;
    const int dir = blockIdx.x / NBPD;
    const int cb  = blockIdx.x % NBPD;
    const int u0  = cb * 8;

    const float* xpd = xp  + (size_t)dir * Bq * T * Gq;
    const float* Wd  = Whh + (size_t)dir * Gq * Hq;
    float* hP[2] = { hA + dir * Bq * Hq, hB + dir * Bq * Hq };
    float* cD   = cSt + dir * Bq * Hq;

    // ---- preload W tile: Ws[k][gc] = Wd[gate*512 + u0 + uu][k] ----
    for (int i = tid; i < 32 * 128; i += 256) {
        const int gc = i >> 7;        // 0..31
        const int kq = i & 127;       // float4 index along K
        const int wrow = ((gc >> 3) << 9) + u0 + (gc & 7);
        const float4 v = *(const float4*)(Wd + (size_t)wrow * Hq + kq * 4);
        const int k = kq * 4;
        Ws[(k + 0) * WS_S + gc] = v.x;
        Ws[(k + 1) * WS_S + gc] = v.y;
        Ws[(k + 2) * WS_S + gc] = v.z;
        Ws[(k + 3) * WS_S + gc] = v.w;
    }

    // ---- init h, c for owned units ----
    for (int i = tid; i < 512; i += 256) {
        const int b = i >> 3, uu = i & 7;
        const int u = u0 + uu;
        hP[0][b * Hq + u] = h0 ? h0[b * Hq + u] : 0.f;
        cD   [b * Hq + u] = c0 ? c0[b * Hq + u] : 0.f;
    }
    gridBarrier();

    int ping = 0;
    for (int t = 0; t < T; t++) {
        const int tt = (dir == 1 && revDir1) ? (T - 1 - t) : t;
        const float* hI = hP[ping];
        float*       hO = hP[1 - ping];

        float acc[4][2] = {{0.f,0.f},{0.f,0.f},{0.f,0.f},{0.f,0.f}};

        for (int k0 = 0; k0 < Hq; k0 += 32) {
            // stage h chunk: Hs[k][b]
#pragma unroll
            for (int q = tid; q < 512; q += 256) {
                const int b = q >> 3, quad = q & 7;
                const float4 v = __ldcg((const float4*)(hI + b * Hq + k0 + quad * 4));
                const int k = quad * 4;
                Hs[(k + 0) * HS_S + b] = v.x;
                Hs[(k + 1) * HS_S + b] = v.y;
                Hs[(k + 2) * HS_S + b] = v.z;
                Hs[(k + 3) * HS_S + b] = v.w;
            }
            __syncthreads();
#pragma unroll
            for (int k = 0; k < 32; k++) {
                const float4 a = *(const float4*)&Hs[k * HS_S + ty * 4];
                const float2 b = *(const float2*)&Ws[(k0 + k) * WS_S + tx * 2];
                acc[0][0] += a.x * b.x; acc[0][1] += a.x * b.y;
                acc[1][0] += a.y * b.x; acc[1][1] += a.y * b.y;
                acc[2][0] += a.z * b.x; acc[2][1] += a.z * b.y;
                acc[3][0] += a.w * b.x; acc[3][1] += a.w * b.y;
            }
            __syncthreads();
        }

        // add input projection, stash gates
#pragma unroll
        for (int i = 0; i < 4; i++) {
            const int b = ty * 4 + i;
#pragma unroll
            for (int j = 0; j < 2; j++) {
                const int gc = tx * 2 + j;
                const int gate = gc >> 3, uu = gc & 7;
                Gs[b * GS_S + gc] = acc[i][j] +
                    xpd[((size_t)b * T + tt) * Gq + (gate << 9) + u0 + uu];
            }
        }
        __syncthreads();

        // cell update
#pragma unroll
        for (int i = tid; i < 512; i += 256) {
            const int b = i >> 3, uu = i & 7;
            const float iv = Gs[b * GS_S + uu];
            const float fv = Gs[b * GS_S + 8 + uu];
            const float gv = Gs[b * GS_S + 16 + uu];
            const float ov = Gs[b * GS_S + 24 + uu];
            const int u = u0 + uu;
            const float cOld = cD[b * Hq + u];
            const float si = 1.f / (1.f + expf(-iv));
            const float sf = 1.f / (1.f + expf(-fv));
            const float so = 1.f / (1.f + expf(-ov));
            const float cN = sf * cOld + si * tanhf(gv);
            const float hN = so * tanhf(cN);
            cD[b * Hq + u] = cN;
            hO[b * Hq + u] = hN;
            y[((size_t)b * T + tt) * yStride + dir * yDirMult + u] = hN;
        }

        gridBarrier();
        ping ^= 1;
    }

    // final states into stacked [b][dir*512+u] layout (encoder only)
    if (hFin) {
        for (int i = tid; i < 512; i += 256) {
            const int b = i >> 3, uu = i & 7;
            const int u = u0 + uu;
            hFin[b * 1024 + dir * 512 + u] = hP[ping][b * Hq + u];
            cFin[b * 1024 + dir * 512 + u] = cD[b * Hq + u];
        }
    }
}

// decoder input: concat(tgt_in, sc_emb[scenario[b]])
__global__ void build_dcat(const float* __restrict__ tgt, const float* __restrict__ scEmb,
                           const int* __restrict__ scen, float* __restrict__ out)
{
    const size_t i = (size_t)blockIdx.x * 256 + threadIdx.x;
    if (i >= (size_t)Bq * TDq * 640) return;
    const int r = (int)(i / 640);
    const int j = (int)(i - (size_t)r * 640);
    float v;
    if (j < 128) v = tgt[(size_t)r * 128 + j];
    else         v = scEmb[scen[r / TDq] * 512 + (j - 128)];
    out[i] = v;
}

// ---------------------------------------------------------------------------
extern "C" void kernel_launch(void* const* d_in, const int* in_sizes, int n_in,
                              void* d_out, int out_size)
{
    (void)in_sizes; (void)n_in; (void)out_size;
    const float* src   = (const float*)d_in[0];
    const float* tgt   = (const float*)d_in[1];
    const int*   scen  = (const int*)  d_in[2];
    const float* eWih0 = (const float*)d_in[3];
    const float* eWhh0 = (const float*)d_in[4];
    const float* eB0   = (const float*)d_in[5];
    const float* eWih  = (const float*)d_in[6];
    const float* eWhh  = (const float*)d_in[7];
    const float* eB    = (const float*)d_in[8];
    const float* hbW   = (const float*)d_in[9];
    const float* hbB   = (const float*)d_in[10];
    const float* cbW   = (const float*)d_in[11];
    const float* cbB   = (const float*)d_in[12];
    const float* scEmb = (const float*)d_in[13];
    const float* dWih0 = (const float*)d_in[14];
    const float* dWhh0 = (const float*)d_in[15];
    const float* dB0   = (const float*)d_in[16];
    const float* dWih  = (const float*)d_in[17];
    const float* dWhh  = (const float*)d_in[18];
    const float* dB    = (const float*)d_in[19];
    const float* outW  = (const float*)d_in[20];
    const float* outB  = (const float*)d_in[21];
    float* out = (float*)d_out;

    float *xp, *X0, *X1, *dcat, *hwork, *cst, *hsP, *csP, *h0P, *c0P;
    cudaGetSymbolAddress((void**)&xp,    g_xp);
    cudaGetSymbolAddress((void**)&X0,    g_X0);
    cudaGetSymbolAddress((void**)&X1,    g_X1);
    cudaGetSymbolAddress((void**)&dcat,  g_dcat);
    cudaGetSymbolAddress((void**)&hwork, g_hwork);
    cudaGetSymbolAddress((void**)&cst,   g_cwork);
    cudaGetSymbolAddress((void**)&hsP,   g_hs);
    cudaGetSymbolAddress((void**)&csP,   g_cs);
    cudaGetSymbolAddress((void**)&h0P,   g_h0);
    cudaGetSymbolAddress((void**)&c0P,   g_c0);
    float* hA = hwork;
    float* hB = hwork + 2 * Bq * Hq;

    const size_t smemB = SMEM_FLOATS * sizeof(float);
    cudaFuncSetAttribute(lstm_persist, cudaFuncAttributeMaxDynamicSharedMemorySize, (int)smemB);

    // ======================= encoder =======================
    const float* Xin = src;
    int inDim = Fq;
    float* Xcur = X0;
    for (int l = 0; l < Lq; l++) {
        const float* Wih = l ? eWih + (size_t)(l - 1) * 2 * Gq * 1024 : eWih0;
        const float* bih = l ? eB   + (size_t)(l - 1) * 2 * Gq        : eB0;
        const size_t wZ = (size_t)Gq * inDim;
        gemm128<<<dim3(Gq / 128, (Bq * TSq) / 128, 2), 256>>>(
            Xin, Wih, bih, xp, Bq * TSq, Gq, inDim,
            0, wZ, (size_t)Gq, (size_t)Bq * TSq * Gq, 0);

        const float* Whh = l ? eWhh + (size_t)(l - 1) * 2 * Gq * Hq : eWhh0;
        lstm_persist<<<2 * NBPD, 256, smemB>>>(
            xp, Whh, nullptr, nullptr, hA, hB, cst, Xcur,
            hsP + (size_t)l * Bq * 1024, csP + (size_t)l * Bq * 1024,
            TSq, /*rev dir1*/1, /*yStride*/1024, /*yDirMult*/512);

        Xin = Xcur; inDim = 1024;
        Xcur = (Xcur == X0) ? X1 : X0;
    }

    // ======================= bridges (tanh GEMMs) =======================
    gemm128<<<dim3(Hq / 128, (Lq * Bq) / 128, 1), 256>>>(
        hsP, hbW, hbB, h0P, Lq * Bq, Hq, 1024, 0, 0, 0, 0, 1);
    gemm128<<<dim3(Hq / 128, (Lq * Bq) / 128, 1), 256>>>(
        csP, cbW, cbB, c0P, Lq * Bq, Hq, 1024, 0, 0, 0, 0, 1);

    // ======================= decoder =======================
    build_dcat<<<(int)(((size_t)Bq * TDq * 640 + 255) / 256), 256>>>(tgt, scEmb, scen, dcat);

    Xin = dcat; inDim = Fq + Hq;   // 640
    for (int l = 0; l < Lq; l++) {
        const float* Wih = l ? dWih + (size_t)(l - 1) * Gq * Hq : dWih0;
        const float* bih = l ? dB   + (size_t)(l - 1) * Gq      : dB0;
        gemm128<<<dim3(Gq / 128, (Bq * TDq) / 128, 1), 256>>>(
            Xin, Wih, bih, xp, Bq * TDq, Gq, inDim, 0, 0, 0, 0, 0);

        const float* Whh = l ? dWhh + (size_t)(l - 1) * Gq * Hq : dWhh0;
        lstm_persist<<<NBPD, 256, smemB>>>(
            xp, Whh, h0P + (size_t)l * Bq * Hq, c0P + (size_t)l * Bq * Hq,
            hA, hB, cst, Xcur, nullptr, nullptr,
            TDq, 0, /*yStride*/512, /*yDirMult*/0);

        Xin = Xcur; inDim = Hq;
        Xcur = (Xcur == X0) ? X1 : X0;
    }

    // output projection straight into d_out
    gemm128<<<dim3(Fq / 128, (Bq * TDq) / 128, 1), 256>>>(
        Xin, outW, outB, out, Bq * TDq, Fq, Hq, 0, 0, 0, 0, 0);
}

// round 3
// speedup vs baseline: 1.1006x; 1.1006x over previous
#include <cuda_runtime.h>
#include <math.h>
#include <stdint.h>

#define Bq 64
#define TSq 300
#define TDq 180
#define Fq 128
#define Hq 512
#define Lq 4
#define Gq 2048   // 4*H

// ---------------- static device scratch (no runtime allocation) ----------------
__device__ float g_xp[(size_t)2 * Bq * TSq * Gq];
__device__ float g_X0[(size_t)Bq * TSq * 1024];
__device__ float g_X1[(size_t)Bq * TSq * 1024];
__device__ float g_dcat[(size_t)Bq * TDq * 640];
__device__ float g_hwork[2][2 * Bq * Hq];
__device__ float g_cwork[2 * Bq * Hq];
__device__ float g_hs[Lq * Bq * 1024];
__device__ float g_cs[Lq * Bq * 1024];
__device__ float g_h0[Lq * Bq * Hq];
__device__ float g_c0[Lq * Bq * Hq];
__device__ unsigned g_barCnt;
__device__ unsigned g_barGen;

// -------- packed f32x2 helpers --------
#define FMA_F32X2(acc, a, b) \
    asm("fma.rn.f32x2 %0, %1, %2, %0;" : "+l"(acc) : "l"(a), "l"(b))
#define PACK_DUP(out, v) do { \
    unsigned _u = __float_as_uint(v); \
    asm("mov.b64 %0, {%1, %1};" : "=l"(out) : "r"(_u)); } while (0)
#define UNPACK_2(lo, hi, in) \
    asm("mov.b64 {%0, %1}, %2;" : "=r"(lo), "=r"(hi) : "l"(in))

// ---------------------------------------------------------------------------
// software grid barrier (all blocks co-resident by construction: grid<=128)
// ---------------------------------------------------------------------------
__device__ __forceinline__ void gridBarrier()
{
    __syncthreads();
    if (threadIdx.x == 0) {
        const unsigned gen = *((volatile unsigned*)&g_barGen);
        __threadfence();
        if (atomicAdd(&g_barCnt, 1u) == gridDim.x - 1u) {
            atomicExch(&g_barCnt, 0u);
            __threadfence();
            atomicAdd(&g_barGen, 1u);
        } else {
            while (*((volatile unsigned*)&g_barGen) == gen) { __nanosleep(64); }
        }
        __threadfence();
    }
    __syncthreads();
}

// ---------------------------------------------------------------------------
// Tiled fp32 GEMM with packed f32x2 FMA: C[M,N] = A[M,K] @ W[N,K]^T + bias
// BM=BN=128, BK=8, 256 threads, 8x8 micro-tile as 4 row-pairs x 8 cols.
// ---------------------------------------------------------------------------
__global__ __launch_bounds__(256, 2)
void gemm128(const float* __restrict__ A, const float* __restrict__ W,
             const float* __restrict__ bias, float* __restrict__ C,
             int M, int N, int K,
             size_t aZ, size_t wZ, size_t bZ, size_t cZ, int act)
{
    A    += blockIdx.z * aZ;
    W    += blockIdx.z * wZ;
    bias += blockIdx.z * bZ;
    C    += blockIdx.z * cZ;
    const int n0 = blockIdx.x * 128;
    const int m0 = blockIdx.y * 128;

    __shared__ float As[8][128];
    __shared__ float Bs[8][128];

    const int tid = threadIdx.x;
    const int ty = tid >> 4, tx = tid & 15;
    const int lrow = tid >> 1;
    const int lq   = (tid & 1) * 4;

    unsigned long long accp[4][8];
#pragma unroll
    for (int i = 0; i < 4; i++)
#pragma unroll
        for (int j = 0; j < 8; j++) accp[i][j] = 0ull;

    for (int k0 = 0; k0 < K; k0 += 8) {
        float4 av = *(const float4*)(A + (size_t)(m0 + lrow) * K + k0 + lq);
        float4 wv = *(const float4*)(W + (size_t)(n0 + lrow) * K + k0 + lq);
        As[lq + 0][lrow] = av.x; As[lq + 1][lrow] = av.y;
        As[lq + 2][lrow] = av.z; As[lq + 3][lrow] = av.w;
        Bs[lq + 0][lrow] = wv.x; Bs[lq + 1][lrow] = wv.y;
        Bs[lq + 2][lrow] = wv.z; Bs[lq + 3][lrow] = wv.w;
        __syncthreads();
#pragma unroll
        for (int k = 0; k < 8; k++) {
            unsigned long long ap[4];
#pragma unroll
            for (int pi = 0; pi < 4; pi++)
                ap[pi] = *(const unsigned long long*)&As[k][ty * 8 + 2 * pi];
            const float4 b0 = *(const float4*)&Bs[k][tx * 8];
            const float4 b1 = *(const float4*)&Bs[k][tx * 8 + 4];
            unsigned long long bd[8];
            PACK_DUP(bd[0], b0.x); PACK_DUP(bd[1], b0.y);
            PACK_DUP(bd[2], b0.z); PACK_DUP(bd[3], b0.w);
            PACK_DUP(bd[4], b1.x); PACK_DUP(bd[5], b1.y);
            PACK_DUP(bd[6], b1.z); PACK_DUP(bd[7], b1.w);
#pragma unroll
            for (int pi = 0; pi < 4; pi++)
#pragma unroll
                for (int j = 0; j < 8; j++)
                    FMA_F32X2(accp[pi][j], ap[pi], bd[j]);
        }
        __syncthreads();
    }

#pragma unroll
    for (int pi = 0; pi < 4; pi++) {
        const size_t mA = (size_t)(m0 + ty * 8 + 2 * pi);
#pragma unroll
        for (int j = 0; j < 8; j++) {
            const int n = n0 + tx * 8 + j;
            unsigned lo, hi;
            UNPACK_2(lo, hi, accp[pi][j]);
            float vlo = __uint_as_float(lo) + bias[n];
            float vhi = __uint_as_float(hi) + bias[n];
            if (act) { vlo = tanhf(vlo); vhi = tanhf(vhi); }
            C[mA * N + n]       = vlo;
            C[(mA + 1) * N + n] = vhi;
        }
    }
}

// ---------------------------------------------------------------------------
// Persistent LSTM layer (templated on batch-count per block).
// NB=64: encoder, grid = 2 dirs x 64 unit-groups.
// NB=32: decoder, grid = 2 batch-halves x 64 unit-groups.
// Block owns 8 hidden units (32 gate cols) x NB batches. Whh resident in smem.
// h chunks double-buffered: LDG prefetch of chunk c+1 overlaps compute of c.
// smem: Ws[512][34] | Hs[2][NB][36] | Gs[NB][33]
// ---------------------------------------------------------------------------
#define WS_S 34
#define HS_S 36
#define GS_S 33

template<int NB>
__global__ __launch_bounds__(256)
void lstm_persist(const float* __restrict__ xp, const float* __restrict__ Whh,
                  const float* __restrict__ h0, const float* __restrict__ c0,
                  float* __restrict__ hA, float* __restrict__ hB,
                  float* __restrict__ cSt, float* __restrict__ y,
                  float* __restrict__ hFin, float* __restrict__ cFin,
                  int T, int revDir1, int yStride, int yDirMult)
{
    constexpr int BY = NB / 16;
    extern __shared__ float sm[];
    float* Ws  = sm;                        // [512][34]
    float* Hs0 = sm + 512 * WS_S;           // [NB][36]
    float* Hs1 = Hs0 + NB * HS_S;           // [NB][36]
    float* Gs  = Hs1 + NB * HS_S;           // [NB][33]

    const int tid = threadIdx.x;
    const int ty = tid >> 4, tx = tid & 15;
    int dir, ub, bOff;
    if (NB == 64) { dir = blockIdx.x >> 6; ub = blockIdx.x & 63; bOff = 0; }
    else          { dir = 0; ub = blockIdx.x & 63; bOff = (blockIdx.x >> 6) * 32; }
    const int u0 = ub * 8;

    const float* xpd = xp  + (size_t)dir * Bq * T * Gq;
    const float* Wd  = Whh + (size_t)dir * Gq * Hq;
    float* hArr[2] = { hA + dir * Bq * Hq, hB + dir * Bq * Hq };
    float* cD = cSt + dir * Bq * Hq;

    // ---- preload W tile: Ws[k][gc] = Wd[gate*512 + u0 + uu][k] ----
    for (int i = tid; i < 32 * 128; i += 256) {
        const int gc = i >> 7;
        const int kq = i & 127;
        const int wrow = ((gc >> 3) << 9) + u0 + (gc & 7);
        const float4 v = *(const float4*)(Wd + (size_t)wrow * Hq + kq * 4);
        const int k = kq * 4;
        Ws[(k + 0) * WS_S + gc] = v.x;
        Ws[(k + 1) * WS_S + gc] = v.y;
        Ws[(k + 2) * WS_S + gc] = v.z;
        Ws[(k + 3) * WS_S + gc] = v.w;
    }

    // ---- init h, c for owned (batch x unit) slice ----
    for (int i = tid; i < NB * 8; i += 256) {
        const int b = bOff + (i >> 3), uu = i & 7, u = u0 + uu;
        hArr[0][b * Hq + u] = h0 ? h0[b * Hq + u] : 0.f;
        cD        [b * Hq + u] = c0 ? c0[b * Hq + u] : 0.f;
    }
    gridBarrier();

    const int sb = tid >> 3;   // staging local batch (0..31)
    const int sq = tid & 7;    // staging k-quad
    float* bufs[2] = { Hs0, Hs1 };

    int ping = 0;
    for (int t = 0; t < T; t++) {
        const int tt = (dir == 1 && revDir1) ? (T - 1 - t) : t;
        const float* hI = hArr[ping];
        float*       hO = hArr[ping ^ 1];

        // stage chunk 0
        float4 p0 = __ldcg((const float4*)(hI + (size_t)(bOff + sb) * Hq + sq * 4));
        float4 p1;
        if (NB == 64) p1 = __ldcg((const float4*)(hI + (size_t)(bOff + sb + 32) * Hq + sq * 4));
        *(float4*)&Hs0[sb * HS_S + sq * 4] = p0;
        if (NB == 64) *(float4*)&Hs0[(sb + 32) * HS_S + sq * 4] = p1;

        float acc[BY][2];
#pragma unroll
        for (int i = 0; i < BY; i++) { acc[i][0] = 0.f; acc[i][1] = 0.f; }

#pragma unroll 1
        for (int c = 0; c < 16; c++) {
            const int k0 = c * 32;
            if (c < 15) {
                p0 = __ldcg((const float4*)(hI + (size_t)(bOff + sb) * Hq + k0 + 32 + sq * 4));
                if (NB == 64)
                    p1 = __ldcg((const float4*)(hI + (size_t)(bOff + sb + 32) * Hq + k0 + 32 + sq * 4));
            }
            __syncthreads();
            const float* Hc = bufs[c & 1];
#pragma unroll
            for (int k = 0; k < 32; k++) {
                float a[BY];
#pragma unroll
                for (int i = 0; i < BY; i++) a[i] = Hc[(ty * BY + i) * HS_S + k];
                const float2 bb = *(const float2*)&Ws[(k0 + k) * WS_S + tx * 2];
#pragma unroll
                for (int i = 0; i < BY; i++) {
                    acc[i][0] += a[i] * bb.x;
                    acc[i][1] += a[i] * bb.y;
                }
            }
            if (c < 15) {
                float* Hn = bufs[(c + 1) & 1];
                *(float4*)&Hn[sb * HS_S + sq * 4] = p0;
                if (NB == 64) *(float4*)&Hn[(sb + 32) * HS_S + sq * 4] = p1;
            }
        }

        // add input projection, stash gates
        __syncthreads();
#pragma unroll
        for (int i = 0; i < BY; i++) {
            const int b = ty * BY + i;
#pragma unroll
            for (int j = 0; j < 2; j++) {
                const int gc = tx * 2 + j;
                const int gate = gc >> 3, uu = gc & 7;
                Gs[b * GS_S + gc] = acc[i][j] +
                    xpd[((size_t)(bOff + b) * T + tt) * Gq + (gate << 9) + u0 + uu];
            }
        }
        __syncthreads();

        // cell update
#pragma unroll
        for (int i = tid; i < NB * 8; i += 256) {
            const int bl = i >> 3, uu = i & 7;
            const int b = bOff + bl, u = u0 + uu;
            const float iv = Gs[bl * GS_S + uu];
            const float fv = Gs[bl * GS_S + 8 + uu];
            const float gv = Gs[bl * GS_S + 16 + uu];
            const float ov = Gs[bl * GS_S + 24 + uu];
            const float cOld = cD[b * Hq + u];
            const float si = 1.f / (1.f + expf(-iv));
            const float sf = 1.f / (1.f + expf(-fv));
            const float so = 1.f / (1.f + expf(-ov));
            const float cN = sf * cOld + si * tanhf(gv);
            const float hN = so * tanhf(cN);
            cD[b * Hq + u] = cN;
            hO[b * Hq + u] = hN;
            y[((size_t)b * T + tt) * yStride + dir * yDirMult + u] = hN;
        }

        gridBarrier();
        ping ^= 1;
    }

    if (hFin) {
        for (int i = tid; i < NB * 8; i += 256) {
            const int b = bOff + (i >> 3), uu = i & 7, u = u0 + uu;
            hFin[b * 1024 + dir * 512 + u] = hArr[ping][b * Hq + u];
            cFin[b * 1024 + dir * 512 + u] = cD[b * Hq + u];
        }
    }
}

// decoder input: concat(tgt_in, sc_emb[scenario[b]])
__global__ void build_dcat(const float* __restrict__ tgt, const float* __restrict__ scEmb,
                           const int* __restrict__ scen, float* __restrict__ out)
{
    const size_t i = (size_t)blockIdx.x * 256 + threadIdx.x;
    if (i >= (size_t)Bq * TDq * 640) return;
    const int r = (int)(i / 640);
    const int j = (int)(i - (size_t)r * 640);
    float v;
    if (j < 128) v = tgt[(size_t)r * 128 + j];
    else         v = scEmb[scen[r / TDq] * 512 + (j - 128)];
    out[i] = v;
}

// ---------------------------------------------------------------------------
extern "C" void kernel_launch(void* const* d_in, const int* in_sizes, int n_in,
                              void* d_out, int out_size)
{
    (void)in_sizes; (void)n_in; (void)out_size;
    const float* src   = (const float*)d_in[0];
    const float* tgt   = (const float*)d_in[1];
    const int*   scen  = (const int*)  d_in[2];
    const float* eWih0 = (const float*)d_in[3];
    const float* eWhh0 = (const float*)d_in[4];
    const float* eB0   = (const float*)d_in[5];
    const float* eWih  = (const float*)d_in[6];
    const float* eWhh  = (const float*)d_in[7];
    const float* eB    = (const float*)d_in[8];
    const float* hbW   = (const float*)d_in[9];
    const float* hbB   = (const float*)d_in[10];
    const float* cbW   = (const float*)d_in[11];
    const float* cbB   = (const float*)d_in[12];
    const float* scEmb = (const float*)d_in[13];
    const float* dWih0 = (const float*)d_in[14];
    const float* dWhh0 = (const float*)d_in[15];
    const float* dB0   = (const float*)d_in[16];
    const float* dWih  = (const float*)d_in[17];
    const float* dWhh  = (const float*)d_in[18];
    const float* dB    = (const float*)d_in[19];
    const float* outW  = (const float*)d_in[20];
    const float* outB  = (const float*)d_in[21];
    float* out = (float*)d_out;

    float *xp, *X0, *X1, *dcat, *hwork, *cst, *hsP, *csP, *h0P, *c0P;
    cudaGetSymbolAddress((void**)&xp,    g_xp);
    cudaGetSymbolAddress((void**)&X0,    g_X0);
    cudaGetSymbolAddress((void**)&X1,    g_X1);
    cudaGetSymbolAddress((void**)&dcat,  g_dcat);
    cudaGetSymbolAddress((void**)&hwork, g_hwork);
    cudaGetSymbolAddress((void**)&cst,   g_cwork);
    cudaGetSymbolAddress((void**)&hsP,   g_hs);
    cudaGetSymbolAddress((void**)&csP,   g_cs);
    cudaGetSymbolAddress((void**)&h0P,   g_h0);
    cudaGetSymbolAddress((void**)&c0P,   g_c0);
    float* hA = hwork;
    float* hB = hwork + 2 * Bq * Hq;

    const size_t smemEnc = (512 * WS_S + 2 * 64 * HS_S + 64 * GS_S) * sizeof(float);
    const size_t smemDec = (512 * WS_S + 2 * 32 * HS_S + 32 * GS_S) * sizeof(float);
    cudaFuncSetAttribute(lstm_persist<64>, cudaFuncAttributeMaxDynamicSharedMemorySize, (int)smemEnc);
    cudaFuncSetAttribute(lstm_persist<32>, cudaFuncAttributeMaxDynamicSharedMemorySize, (int)smemDec);

    // ======================= encoder =======================
    const float* Xin = src;
    int inDim = Fq;
    float* Xcur = X0;
    for (int l = 0; l < Lq; l++) {
        const float* Wih = l ? eWih + (size_t)(l - 1) * 2 * Gq * 1024 : eWih0;
        const float* bih = l ? eB   + (size_t)(l - 1) * 2 * Gq        : eB0;
        const size_t wZ = (size_t)Gq * inDim;
        gemm128<<<dim3(Gq / 128, (Bq * TSq) / 128, 2), 256>>>(
            Xin, Wih, bih, xp, Bq * TSq, Gq, inDim,
            0, wZ, (size_t)Gq, (size_t)Bq * TSq * Gq, 0);

        const float* Whh = l ? eWhh + (size_t)(l - 1) * 2 * Gq * Hq : eWhh0;
        lstm_persist<64><<<128, 256, smemEnc>>>(
            xp, Whh, nullptr, nullptr, hA, hB, cst, Xcur,
            hsP + (size_t)l * Bq * 1024, csP + (size_t)l * Bq * 1024,
            TSq, 1, 1024, 512);

        Xin = Xcur; inDim = 1024;
        Xcur = (Xcur == X0) ? X1 : X0;
    }

    // ======================= bridges (tanh GEMMs) =======================
    gemm128<<<dim3(Hq / 128, (Lq * Bq) / 128, 1), 256>>>(
        hsP, hbW, hbB, h0P, Lq * Bq, Hq, 1024, 0, 0, 0, 0, 1);
    gemm128<<<dim3(Hq / 128, (Lq * Bq) / 128, 1), 256>>>(
        csP, cbW, cbB, c0P, Lq * Bq, Hq, 1024, 0, 0, 0, 0, 1);

    // ======================= decoder =======================
    build_dcat<<<(int)(((size_t)Bq * TDq * 640 + 255) / 256), 256>>>(tgt, scEmb, scen, dcat);

    Xin = dcat; inDim = Fq + Hq;
    for (int l = 0; l < Lq; l++) {
        const float* Wih = l ? dWih + (size_t)(l - 1) * Gq * Hq : dWih0;
        const float* bih = l ? dB   + (size_t)(l - 1) * Gq      : dB0;
        gemm128<<<dim3(Gq / 128, (Bq * TDq) / 128, 1), 256>>>(
            Xin, Wih, bih, xp, Bq * TDq, Gq, inDim, 0, 0, 0, 0, 0);

        const float* Whh = l ? dWhh + (size_t)(l - 1) * Gq * Hq : dWhh0;
        lstm_persist<32><<<128, 256, smemDec>>>(
            xp, Whh, h0P + (size_t)l * Bq * Hq, c0P + (size_t)l * Bq * Hq,
            hA, hB, cst, Xcur, nullptr, nullptr,
            TDq, 0, 512, 0);

        Xin = Xcur; inDim = Hq;
        Xcur = (Xcur == X0) ? X1 : X0;
    }

    gemm128<<<dim3(Fq / 128, (Bq * TDq) / 128, 1), 256>>>(
        Xin, outW, outB, out, Bq * TDq, Fq, Hq, 0, 0, 0, 0, 0);
}

// round 5
// speedup vs baseline: 1.3964x; 1.2688x over previous
#include <cuda_runtime.h>
#include <cuda_bf16.h>
#include <math.h>
#include <stdint.h>

#define Bq 64
#define TSq 300
#define TDq 180
#define Fq 128
#define Hq 512
#define Lq 4
#define Gq 2048   // 4*H

// ---------------- static device scratch (no runtime allocation) ----------------
__device__ float g_xp[(size_t)2 * Bq * TSq * Gq];
__device__ float g_X0[(size_t)Bq * TSq * 1024];
__device__ float g_X1[(size_t)Bq * TSq * 1024];
__device__ float g_dcat[(size_t)Bq * TDq * 640];
__device__ float g_hwork[2][2 * Bq * Hq];
__device__ float g_cwork[2 * Bq * Hq];
__device__ float g_hs[Lq * Bq * 1024];
__device__ float g_cs[Lq * Bq * 1024];
__device__ float g_h0[Lq * Bq * Hq];
__device__ float g_c0[Lq * Bq * Hq];
__device__ unsigned g_barCnt;
__device__ unsigned g_barGen;
// bf16 split buffers for tensor-core projections
__device__ __nv_bfloat16 g_Ah[(size_t)Bq * TSq * 1024];
__device__ __nv_bfloat16 g_Al[(size_t)Bq * TSq * 1024];
__device__ __nv_bfloat16 g_Wh[(size_t)2 * Gq * 1024];
__device__ __nv_bfloat16 g_Wl[(size_t)2 * Gq * 1024];

// -------- packed f32x2 helpers (bridge/output GEMM) --------
#define FMA_F32X2(acc, a, b) \
    asm("fma.rn.f32x2 %0, %1, %2, %0;" : "+l"(acc) : "l"(a), "l"(b))
#define PACK_DUP(out, v) do { \
    unsigned _u = __float_as_uint(v); \
    asm("mov.b64 %0, {%1, %1};" : "=l"(out) : "r"(_u)); } while (0)
#define UNPACK_2(lo, hi, in) \
    asm("mov.b64 {%0, %1}, %2;" : "=r"(lo), "=r"(hi) : "l"(in))

// -------- mma.sync / ldmatrix / cp.async helpers (arch-generic, compute_103-safe) -----
__device__ __forceinline__ uint32_t smem_u32(const void* p) {
    uint32_t a;
    asm("{ .reg .u64 t; cvta.to.shared.u64 t, %1; cvt.u32.u64 %0, t; }" : "=r"(a) : "l"(p));
    return a;
}
#define LDM_X4(r0, r1, r2, r3, addr) \
    asm volatile("ldmatrix.sync.aligned.m8n8.x4.shared.b16 {%0,%1,%2,%3}, [%4];" \
        : "=r"(r0), "=r"(r1), "=r"(r2), "=r"(r3) : "r"(addr))
#define MMA_BF16(c0, c1, c2, c3, a0, a1, a2, a3, b0, b1) \
    asm volatile("mma.sync.aligned.m16n8k16.row.col.f32.bf16.bf16.f32 " \
        "{%0,%1,%2,%3}, {%4,%5,%6,%7}, {%8,%9}, {%0,%1,%2,%3};" \
        : "+f"(c0), "+f"(c1), "+f"(c2), "+f"(c3) \
        : "r"(a0), "r"(a1), "r"(a2), "r"(a3), "r"(b0), "r"(b1))
#define CPA16(dst, src) \
    asm volatile("cp.async.cg.shared.global [%0], [%1], 16;" :: "r"(dst), "l"(src))
#define CPA_COMMIT() asm volatile("cp.async.commit_group;" ::: "memory")
#define CPA_WAIT(n)  asm volatile("cp.async.wait_group %0;" :: "n"(n) : "memory")

// ---------------------------------------------------------------------------
// software grid barrier (all blocks co-resident by construction: grid<=128)
// ---------------------------------------------------------------------------
__device__ __forceinline__ void gridBarrier()
{
    __syncthreads();
    if (threadIdx.x == 0) {
        const unsigned gen = *((volatile unsigned*)&g_barGen);
        __threadfence();
        if (atomicAdd(&g_barCnt, 1u) == gridDim.x - 1u) {
            atomicExch(&g_barCnt, 0u);
            __threadfence();
            atomicAdd(&g_barGen, 1u);
        } else {
            while (*((volatile unsigned*)&g_barGen) == gen) { __nanosleep(64); }
        }
        __threadfence();
    }
    __syncthreads();
}

// ---------------------------------------------------------------------------
// fp32 -> bf16 hi/lo split (elementwise), n % 4 == 0
// ---------------------------------------------------------------------------
__global__ void conv_split(const float* __restrict__ in, __nv_bfloat16* __restrict__ hi,
                           __nv_bfloat16* __restrict__ lo, size_t n)
{
    const size_t i = ((size_t)blockIdx.x * 256 + threadIdx.x) * 4;
    if (i >= n) return;
    const float4 v = *(const float4*)(in + i);
    __nv_bfloat16 h0 = __float2bfloat16(v.x), h1 = __float2bfloat16(v.y);
    __nv_bfloat16 h2 = __float2bfloat16(v.z), h3 = __float2bfloat16(v.w);
    __nv_bfloat16 l0 = __float2bfloat16(v.x - __bfloat162float(h0));
    __nv_bfloat16 l1 = __float2bfloat16(v.y - __bfloat162float(h1));
    __nv_bfloat16 l2 = __float2bfloat16(v.z - __bfloat162float(h2));
    __nv_bfloat16 l3 = __float2bfloat16(v.w - __bfloat162float(h3));
    __nv_bfloat162 hp0(h0, h1), hp1(h2, h3), lp0(l0, l1), lp1(l2, l3);
    *(uint2*)(hi + i) = make_uint2(*(uint32_t*)&hp0, *(uint32_t*)&hp1);
    *(uint2*)(lo + i) = make_uint2(*(uint32_t*)&lp0, *(uint32_t*)&lp1);
}

// ---------------------------------------------------------------------------
// Split-bf16 tensor-core GEMM via mma.sync: C[M,N] = A[M,K] @ W[N,K]^T + bias
// D = Ah*Wh + Ah*Wl + Al*Wh (fp32 accum). 128x128 CTA tile, 8 warps (2x4),
// warp tile 64x32 via m16n8k16. K chunks of 32, cp.async double-buffered.
// smem tile: [128 rows][64B], XOR swizzle g^=(row&3) on 16B granules.
// M%128==0, N%128==0, K%32==0.
// ---------------------------------------------------------------------------
#define MMA_TILE_B   8192                     // one 128x32 bf16 tile
#define MMA_BUF_B    (4 * MMA_TILE_B)         // Ah|Al|Wh|Wl
#define MMA_SMEM_B   (2 * MMA_BUF_B)          // double buffer = 64KB

__global__ __launch_bounds__(256, 2)
void mma_xp(const __nv_bfloat16* __restrict__ Ah, const __nv_bfloat16* __restrict__ Al,
            const __nv_bfloat16* __restrict__ Wh, const __nv_bfloat16* __restrict__ Wl,
            const float* __restrict__ bias, float* __restrict__ C,
            int M, int N, int K, size_t wZ, size_t bZ, size_t cZ)
{
    extern __shared__ __align__(128) char smem[];
    const uint32_t sbase = smem_u32(smem);

    Wh   += blockIdx.z * wZ;
    Wl   += blockIdx.z * wZ;
    bias += blockIdx.z * bZ;
    C    += blockIdx.z * cZ;
    const int n0 = blockIdx.x * 128;
    const int m0 = blockIdx.y * 128;

    const int tid  = threadIdx.x;
    const int lane = tid & 31;
    const int warp = tid >> 5;
    const int wm = warp >> 2;          // 0..1 : 64-row block
    const int wn = warp & 3;           // 0..3 : 32-col block

    float acc[4][4][4];
#pragma unroll
    for (int i = 0; i < 4; i++)
#pragma unroll
        for (int j = 0; j < 4; j++)
#pragma unroll
            for (int q = 0; q < 4; q++) acc[i][j][q] = 0.f;

    // per-thread cp.async granule mapping (2 granules per tile per thread)
    const int gi0 = tid, gi1 = tid + 256;
    const int r0g = gi0 >> 2, g0 = gi0 & 3;
    const int r1g = gi1 >> 2, g1 = gi1 & 3;
    const uint32_t so0 = (uint32_t)(r0g * 64 + ((g0 ^ (r0g & 3)) << 4));
    const uint32_t so1 = (uint32_t)(r1g * 64 + ((g1 ^ (r1g & 3)) << 4));

    // ldmatrix address components
    const int arow = wm * 64 + (lane & 15);        // + mt*16
    const int aswz = arow & 3;
    const int agoff = lane >> 4;                    // 0/1 : k granule within kstep
    const int brow = wn * 32 + (lane & 7);          // + (p*2 + ntLocal)*8
    const int bgoff = (lane >> 3) & 1;
    const int bnt   = (lane >> 4);                  // 0/1 within pair

    const int nch = K >> 5;

    // prologue: load chunk 0 into buf 0
    {
        const int k0 = 0;
#pragma unroll
        for (int h = 0; h < 2; h++) {
            const int rr = h ? r1g : r0g;
            const int gg = h ? g1 : g0;
            const uint32_t so = h ? so1 : so0;
            const size_t ka = (size_t)k0 + gg * 8;
            CPA16(sbase + 0 * MMA_TILE_B + so, Ah + (size_t)(m0 + rr) * K + ka);
            CPA16(sbase + 1 * MMA_TILE_B + so, Al + (size_t)(m0 + rr) * K + ka);
            CPA16(sbase + 2 * MMA_TILE_B + so, Wh + (size_t)(n0 + rr) * K + ka);
            CPA16(sbase + 3 * MMA_TILE_B + so, Wl + (size_t)(n0 + rr) * K + ka);
        }
        CPA_COMMIT();
    }

    for (int c = 0; c < nch; c++) {
        const uint32_t buf = (uint32_t)(c & 1) * MMA_BUF_B;
        if (c + 1 < nch) {
            const uint32_t nbuf = (uint32_t)((c + 1) & 1) * MMA_BUF_B;
            const int k0 = (c + 1) << 5;
#pragma unroll
            for (int h = 0; h < 2; h++) {
                const int rr = h ? r1g : r0g;
                const int gg = h ? g1 : g0;
                const uint32_t so = h ? so1 : so0;
                const size_t ka = (size_t)k0 + gg * 8;
                CPA16(sbase + nbuf + 0 * MMA_TILE_B + so, Ah + (size_t)(m0 + rr) * K + ka);
                CPA16(sbase + nbuf + 1 * MMA_TILE_B + so, Al + (size_t)(m0 + rr) * K + ka);
                CPA16(sbase + nbuf + 2 * MMA_TILE_B + so, Wh + (size_t)(n0 + rr) * K + ka);
                CPA16(sbase + nbuf + 3 * MMA_TILE_B + so, Wl + (size_t)(n0 + rr) * K + ka);
            }
            CPA_COMMIT();
            CPA_WAIT(1);
        } else {
            CPA_WAIT(0);
        }
        __syncthreads();

        const uint32_t aH = sbase + buf + 0 * MMA_TILE_B;
        const uint32_t aL = sbase + buf + 1 * MMA_TILE_B;
        const uint32_t wH = sbase + buf + 2 * MMA_TILE_B;
        const uint32_t wL = sbase + buf + 3 * MMA_TILE_B;

#pragma unroll
        for (int ks = 0; ks < 2; ks++) {
            uint32_t af[4][4], bh[4][2], bl[4][2];
            // A-hi fragments (4 m-tiles)
#pragma unroll
            for (int mt = 0; mt < 4; mt++) {
                const int rA = arow + mt * 16;
                const uint32_t ad = aH + (uint32_t)(rA * 64 + (((ks * 2 + agoff) ^ aswz) << 4));
                LDM_X4(af[mt][0], af[mt][1], af[mt][2], af[mt][3], ad);
            }
            // W-hi / W-lo fragments (2 ldmatrix.x4 each cover 2 n-tiles)
#pragma unroll
            for (int p = 0; p < 2; p++) {
                const int rB = brow + (p * 2 + bnt) * 8;
                const uint32_t off = (uint32_t)(rB * 64 + (((ks * 2 + bgoff) ^ (rB & 3)) << 4));
                LDM_X4(bh[p * 2][0], bh[p * 2][1], bh[p * 2 + 1][0], bh[p * 2 + 1][1], wH + off);
                LDM_X4(bl[p * 2][0], bl[p * 2][1], bl[p * 2 + 1][0], bl[p * 2 + 1][1], wL + off);
            }
            // term0: Ah*Wh, term1: Ah*Wl
#pragma unroll
            for (int mt = 0; mt < 4; mt++)
#pragma unroll
                for (int nt = 0; nt < 4; nt++) {
                    MMA_BF16(acc[mt][nt][0], acc[mt][nt][1], acc[mt][nt][2], acc[mt][nt][3],
                             af[mt][0], af[mt][1], af[mt][2], af[mt][3],
                             bh[nt][0], bh[nt][1]);
                    MMA_BF16(acc[mt][nt][0], acc[mt][nt][1], acc[mt][nt][2], acc[mt][nt][3],
                             af[mt][0], af[mt][1], af[mt][2], af[mt][3],
                             bl[nt][0], bl[nt][1]);
                }
            // A-lo fragments, term2: Al*Wh
#pragma unroll
            for (int mt = 0; mt < 4; mt++) {
                const int rA = arow + mt * 16;
                const uint32_t ad = aL + (uint32_t)(rA * 64 + (((ks * 2 + agoff) ^ aswz) << 4));
                LDM_X4(af[mt][0], af[mt][1], af[mt][2], af[mt][3], ad);
            }
#pragma unroll
            for (int mt = 0; mt < 4; mt++)
#pragma unroll
                for (int nt = 0; nt < 4; nt++)
                    MMA_BF16(acc[mt][nt][0], acc[mt][nt][1], acc[mt][nt][2], acc[mt][nt][3],
                             af[mt][0], af[mt][1], af[mt][2], af[mt][3],
                             bh[nt][0], bh[nt][1]);
        }
        __syncthreads();
    }

    // epilogue: add bias, store fp32
    const int mE = m0 + wm * 64 + (lane >> 2);
    const int nE = n0 + wn * 32 + (lane & 3) * 2;
#pragma unroll
    for (int mt = 0; mt < 4; mt++) {
#pragma unroll
        for (int nt = 0; nt < 4; nt++) {
            const int m = mE + mt * 16;
            const int n = nE + nt * 8;
            const float b0 = bias[n], b1 = bias[n + 1];
            float2 v0 = make_float2(acc[mt][nt][0] + b0, acc[mt][nt][1] + b1);
            float2 v1 = make_float2(acc[mt][nt][2] + b0, acc[mt][nt][3] + b1);
            *(float2*)(C + (size_t)m * N + n)       = v0;
            *(float2*)(C + (size_t)(m + 8) * N + n) = v1;
        }
    }
}

// ---------------------------------------------------------------------------
// fp32 f32x2 GEMM (small: bridges + output projection)
// ---------------------------------------------------------------------------
__global__ __launch_bounds__(256, 2)
void gemm128(const float* __restrict__ A, const float* __restrict__ W,
             const float* __restrict__ bias, float* __restrict__ C,
             int M, int N, int K,
             size_t aZ, size_t wZ, size_t bZ, size_t cZ, int act)
{
    A    += blockIdx.z * aZ;
    W    += blockIdx.z * wZ;
    bias += blockIdx.z * bZ;
    C    += blockIdx.z * cZ;
    const int n0 = blockIdx.x * 128;
    const int m0 = blockIdx.y * 128;

    __shared__ float As[8][128];
    __shared__ float Bs[8][128];

    const int tid = threadIdx.x;
    const int ty = tid >> 4, tx = tid & 15;
    const int lrow = tid >> 1;
    const int lq   = (tid & 1) * 4;

    unsigned long long accp[4][8];
#pragma unroll
    for (int i = 0; i < 4; i++)
#pragma unroll
        for (int j = 0; j < 8; j++) accp[i][j] = 0ull;

    for (int k0 = 0; k0 < K; k0 += 8) {
        float4 av = *(const float4*)(A + (size_t)(m0 + lrow) * K + k0 + lq);
        float4 wv = *(const float4*)(W + (size_t)(n0 + lrow) * K + k0 + lq);
        As[lq + 0][lrow] = av.x; As[lq + 1][lrow] = av.y;
        As[lq + 2][lrow] = av.z; As[lq + 3][lrow] = av.w;
        Bs[lq + 0][lrow] = wv.x; Bs[lq + 1][lrow] = wv.y;
        Bs[lq + 2][lrow] = wv.z; Bs[lq + 3][lrow] = wv.w;
        __syncthreads();
#pragma unroll
        for (int k = 0; k < 8; k++) {
            unsigned long long ap[4];
#pragma unroll
            for (int pi = 0; pi < 4; pi++)
                ap[pi] = *(const unsigned long long*)&As[k][ty * 8 + 2 * pi];
            const float4 b0 = *(const float4*)&Bs[k][tx * 8];
            const float4 b1 = *(const float4*)&Bs[k][tx * 8 + 4];
            unsigned long long bd[8];
            PACK_DUP(bd[0], b0.x); PACK_DUP(bd[1], b0.y);
            PACK_DUP(bd[2], b0.z); PACK_DUP(bd[3], b0.w);
            PACK_DUP(bd[4], b1.x); PACK_DUP(bd[5], b1.y);
            PACK_DUP(bd[6], b1.z); PACK_DUP(bd[7], b1.w);
#pragma unroll
            for (int pi = 0; pi < 4; pi++)
#pragma unroll
                for (int j = 0; j < 8; j++)
                    FMA_F32X2(accp[pi][j], ap[pi], bd[j]);
        }
        __syncthreads();
    }

#pragma unroll
    for (int pi = 0; pi < 4; pi++) {
        const size_t mA = (size_t)(m0 + ty * 8 + 2 * pi);
#pragma unroll
        for (int j = 0; j < 8; j++) {
            const int n = n0 + tx * 8 + j;
            unsigned lo, hi;
            UNPACK_2(lo, hi, accp[pi][j]);
            float vlo = __uint_as_float(lo) + bias[n];
            float vhi = __uint_as_float(hi) + bias[n];
            if (act) { vlo = tanhf(vlo); vhi = tanhf(vhi); }
            C[mA * N + n]       = vlo;
            C[(mA + 1) * N + n] = vhi;
        }
    }
}

// ---------------------------------------------------------------------------
// Persistent LSTM layer (unchanged from round 3)
// ---------------------------------------------------------------------------
#define WS_S 34
#define HS_S 36
#define GS_S 33

template<int NB>
__global__ __launch_bounds__(256)
void lstm_persist(const float* __restrict__ xp, const float* __restrict__ Whh,
                  const float* __restrict__ h0, const float* __restrict__ c0,
                  float* __restrict__ hA, float* __restrict__ hB,
                  float* __restrict__ cSt, float* __restrict__ y,
                  float* __restrict__ hFin, float* __restrict__ cFin,
                  int T, int revDir1, int yStride, int yDirMult)
{
    constexpr int BY = NB / 16;
    extern __shared__ float sm[];
    float* Ws  = sm;
    float* Hs0 = sm + 512 * WS_S;
    float* Hs1 = Hs0 + NB * HS_S;
    float* Gs  = Hs1 + NB * HS_S;

    const int tid = threadIdx.x;
    const int ty = tid >> 4, tx = tid & 15;
    int dir, ub, bOff;
    if (NB == 64) { dir = blockIdx.x >> 6; ub = blockIdx.x & 63; bOff = 0; }
    else          { dir = 0; ub = blockIdx.x & 63; bOff = (blockIdx.x >> 6) * 32; }
    const int u0 = ub * 8;

    const float* xpd = xp  + (size_t)dir * Bq * T * Gq;
    const float* Wd  = Whh + (size_t)dir * Gq * Hq;
    float* hArr[2] = { hA + dir * Bq * Hq, hB + dir * Bq * Hq };
    float* cD = cSt + dir * Bq * Hq;

    for (int i = tid; i < 32 * 128; i += 256) {
        const int gc = i >> 7;
        const int kq = i & 127;
        const int wrow = ((gc >> 3) << 9) + u0 + (gc & 7);
        const float4 v = *(const float4*)(Wd + (size_t)wrow * Hq + kq * 4);
        const int k = kq * 4;
        Ws[(k + 0) * WS_S + gc] = v.x;
        Ws[(k + 1) * WS_S + gc] = v.y;
        Ws[(k + 2) * WS_S + gc] = v.z;
        Ws[(k + 3) * WS_S + gc] = v.w;
    }

    for (int i = tid; i < NB * 8; i += 256) {
        const int b = bOff + (i >> 3), uu = i & 7, u = u0 + uu;
        hArr[0][b * Hq + u] = h0 ? h0[b * Hq + u] : 0.f;
        cD        [b * Hq + u] = c0 ? c0[b * Hq + u] : 0.f;
    }
    gridBarrier();

    const int sb = tid >> 3;
    const int sq = tid & 7;
    float* bufs[2] = { Hs0, Hs1 };

    int ping = 0;
    for (int t = 0; t < T; t++) {
        const int tt = (dir == 1 && revDir1) ? (T - 1 - t) : t;
        const float* hI = hArr[ping];
        float*       hO = hArr[ping ^ 1];

        float4 p0 = __ldcg((const float4*)(hI + (size_t)(bOff + sb) * Hq + sq * 4));
        float4 p1;
        if (NB == 64) p1 = __ldcg((const float4*)(hI + (size_t)(bOff + sb + 32) * Hq + sq * 4));
        *(float4*)&Hs0[sb * HS_S + sq * 4] = p0;
        if (NB == 64) *(float4*)&Hs0[(sb + 32) * HS_S + sq * 4] = p1;

        float acc[BY][2];
#pragma unroll
        for (int i = 0; i < BY; i++) { acc[i][0] = 0.f; acc[i][1] = 0.f; }

#pragma unroll 1
        for (int c = 0; c < 16; c++) {
            const int k0 = c * 32;
            if (c < 15) {
                p0 = __ldcg((const float4*)(hI + (size_t)(bOff + sb) * Hq + k0 + 32 + sq * 4));
                if (NB == 64)
                    p1 = __ldcg((const float4*)(hI + (size_t)(bOff + sb + 32) * Hq + k0 + 32 + sq * 4));
            }
            __syncthreads();
            const float* Hc = bufs[c & 1];
#pragma unroll
            for (int k = 0; k < 32; k++) {
                float a[BY];
#pragma unroll
                for (int i = 0; i < BY; i++) a[i] = Hc[(ty * BY + i) * HS_S + k];
                const float2 bb = *(const float2*)&Ws[(k0 + k) * WS_S + tx * 2];
#pragma unroll
                for (int i = 0; i < BY; i++) {
                    acc[i][0] += a[i] * bb.x;
                    acc[i][1] += a[i] * bb.y;
                }
            }
            if (c < 15) {
                float* Hn = bufs[(c + 1) & 1];
                *(float4*)&Hn[sb * HS_S + sq * 4] = p0;
                if (NB == 64) *(float4*)&Hn[(sb + 32) * HS_S + sq * 4] = p1;
            }
        }

        __syncthreads();
#pragma unroll
        for (int i = 0; i < BY; i++) {
            const int b = ty * BY + i;
#pragma unroll
            for (int j = 0; j < 2; j++) {
                const int gc = tx * 2 + j;
                const int gate = gc >> 3, uu = gc & 7;
                Gs[b * GS_S + gc] = acc[i][j] +
                    xpd[((size_t)(bOff + b) * T + tt) * Gq + (gate << 9) + u0 + uu];
            }
        }
        __syncthreads();

#pragma unroll
        for (int i = tid; i < NB * 8; i += 256) {
            const int bl = i >> 3, uu = i & 7;
            const int b = bOff + bl, u = u0 + uu;
            const float iv = Gs[bl * GS_S + uu];
            const float fv = Gs[bl * GS_S + 8 + uu];
            const float gv = Gs[bl * GS_S + 16 + uu];
            const float ov = Gs[bl * GS_S + 24 + uu];
            const float cOld = cD[b * Hq + u];
            const float si = 1.f / (1.f + expf(-iv));
            const float sf = 1.f / (1.f + expf(-fv));
            const float so = 1.f / (1.f + expf(-ov));
            const float cN = sf * cOld + si * tanhf(gv);
            const float hN = so * tanhf(cN);
            cD[b * Hq + u] = cN;
            hO[b * Hq + u] = hN;
            y[((size_t)b * T + tt) * yStride + dir * yDirMult + u] = hN;
        }

        gridBarrier();
        ping ^= 1;
    }

    if (hFin) {
        for (int i = tid; i < NB * 8; i += 256) {
            const int b = bOff + (i >> 3), uu = i & 7, u = u0 + uu;
            hFin[b * 1024 + dir * 512 + u] = hArr[ping][b * Hq + u];
            cFin[b * 1024 + dir * 512 + u] = cD[b * Hq + u];
        }
    }
}

// decoder input: concat(tgt_in, sc_emb[scenario[b]])
__global__ void build_dcat(const float* __restrict__ tgt, const float* __restrict__ scEmb,
                           const int* __restrict__ scen, float* __restrict__ out)
{
    const size_t i = (size_t)blockIdx.x * 256 + threadIdx.x;
    if (i >= (size_t)Bq * TDq * 640) return;
    const int r = (int)(i / 640);
    const int j = (int)(i - (size_t)r * 640);
    float v;
    if (j < 128) v = tgt[(size_t)r * 128 + j];
    else         v = scEmb[scen[r / TDq] * 512 + (j - 128)];
    out[i] = v;
}

// ---------------------------------------------------------------------------
extern "C" void kernel_launch(void* const* d_in, const int* in_sizes, int n_in,
                              void* d_out, int out_size)
{
    (void)in_sizes; (void)n_in; (void)out_size;
    const float* src   = (const float*)d_in[0];
    const float* tgt   = (const float*)d_in[1];
    const int*   scen  = (const int*)  d_in[2];
    const float* eWih0 = (const float*)d_in[3];
    const float* eWhh0 = (const float*)d_in[4];
    const float* eB0   = (const float*)d_in[5];
    const float* eWih  = (const float*)d_in[6];
    const float* eWhh  = (const float*)d_in[7];
    const float* eB    = (const float*)d_in[8];
    const float* hbW   = (const float*)d_in[9];
    const float* hbB   = (const float*)d_in[10];
    const float* cbW   = (const float*)d_in[11];
    const float* cbB   = (const float*)d_in[12];
    const float* scEmb = (const float*)d_in[13];
    const float* dWih0 = (const float*)d_in[14];
    const float* dWhh0 = (const float*)d_in[15];
    const float* dB0   = (const float*)d_in[16];
    const float* dWih  = (const float*)d_in[17];
    const float* dWhh  = (const float*)d_in[18];
    const float* dB    = (const float*)d_in[19];
    const float* outW  = (const float*)d_in[20];
    const float* outB  = (const float*)d_in[21];
    float* out = (float*)d_out;

    float *xp, *X0, *X1, *dcat, *hwork, *cst, *hsP, *csP, *h0P, *c0P;
    __nv_bfloat16 *Ah, *Al, *Wh, *Wl;
    cudaGetSymbolAddress((void**)&xp,    g_xp);
    cudaGetSymbolAddress((void**)&X0,    g_X0);
    cudaGetSymbolAddress((void**)&X1,    g_X1);
    cudaGetSymbolAddress((void**)&dcat,  g_dcat);
    cudaGetSymbolAddress((void**)&hwork, g_hwork);
    cudaGetSymbolAddress((void**)&cst,   g_cwork);
    cudaGetSymbolAddress((void**)&hsP,   g_hs);
    cudaGetSymbolAddress((void**)&csP,   g_cs);
    cudaGetSymbolAddress((void**)&h0P,   g_h0);
    cudaGetSymbolAddress((void**)&c0P,   g_c0);
    cudaGetSymbolAddress((void**)&Ah,    g_Ah);
    cudaGetSymbolAddress((void**)&Al,    g_Al);
    cudaGetSymbolAddress((void**)&Wh,    g_Wh);
    cudaGetSymbolAddress((void**)&Wl,    g_Wl);
    float* hA = hwork;
    float* hB = hwork + 2 * Bq * Hq;

    const size_t smemEnc = (512 * WS_S + 2 * 64 * HS_S + 64 * GS_S) * sizeof(float);
    const size_t smemDec = (512 * WS_S + 2 * 32 * HS_S + 32 * GS_S) * sizeof(float);
    cudaFuncSetAttribute(lstm_persist<64>, cudaFuncAttributeMaxDynamicSharedMemorySize, (int)smemEnc);
    cudaFuncSetAttribute(lstm_persist<32>, cudaFuncAttributeMaxDynamicSharedMemorySize, (int)smemDec);
    cudaFuncSetAttribute(mma_xp, cudaFuncAttributeMaxDynamicSharedMemorySize, MMA_SMEM_B);

    const int ME = Bq * TSq;   // 19200
    const int MD = Bq * TDq;   // 11520

    // ======================= encoder =======================
    const float* Xin = src;
    int inDim = Fq;
    float* Xcur = X0;
    for (int l = 0; l < Lq; l++) {
        const float* Wih = l ? eWih + (size_t)(l - 1) * 2 * Gq * 1024 : eWih0;
        const float* bih = l ? eB   + (size_t)(l - 1) * 2 * Gq        : eB0;

        const size_t nA = (size_t)ME * inDim;
        const size_t nW = (size_t)2 * Gq * inDim;
        conv_split<<<(int)((nA / 4 + 255) / 256), 256>>>(Xin, Ah, Al, nA);
        conv_split<<<(int)((nW / 4 + 255) / 256), 256>>>(Wih, Wh, Wl, nW);
        mma_xp<<<dim3(Gq / 128, ME / 128, 2), 256, MMA_SMEM_B>>>(
            Ah, Al, Wh, Wl, bih, xp, ME, Gq, inDim,
            (size_t)Gq * inDim, (size_t)Gq, (size_t)ME * Gq);

        const float* Whh = l ? eWhh + (size_t)(l - 1) * 2 * Gq * Hq : eWhh0;
        lstm_persist<64><<<128, 256, smemEnc>>>(
            xp, Whh, nullptr, nullptr, hA, hB, cst, Xcur,
            hsP + (size_t)l * Bq * 1024, csP + (size_t)l * Bq * 1024,
            TSq, 1, 1024, 512);

        Xin = Xcur; inDim = 1024;
        Xcur = (Xcur == X0) ? X1 : X0;
    }

    // ======================= bridges (tanh GEMMs, fp32) =======================
    gemm128<<<dim3(Hq / 128, (Lq * Bq) / 128, 1), 256>>>(
        hsP, hbW, hbB, h0P, Lq * Bq, Hq, 1024, 0, 0, 0, 0, 1);
    gemm128<<<dim3(Hq / 128, (Lq * Bq) / 128, 1), 256>>>(
        csP, cbW, cbB, c0P, Lq * Bq, Hq, 1024, 0, 0, 0, 0, 1);

    // ======================= decoder =======================
    build_dcat<<<(int)(((size_t)Bq * TDq * 640 + 255) / 256), 256>>>(tgt, scEmb, scen, dcat);

    Xin = dcat; inDim = Fq + Hq;
    for (int l = 0; l < Lq; l++) {
        const float* Wih = l ? dWih + (size_t)(l - 1) * Gq * Hq : dWih0;
        const float* bih = l ? dB   + (size_t)(l - 1) * Gq      : dB0;

        const size_t nA = (size_t)MD * inDim;
        const size_t nW = (size_t)Gq * inDim;
        conv_split<<<(int)((nA / 4 + 255) / 256), 256>>>(Xin, Ah, Al, nA);
        conv_split<<<(int)((nW / 4 + 255) / 256), 256>>>(Wih, Wh, Wl, nW);
        mma_xp<<<dim3(Gq / 128, MD / 128, 1), 256, MMA_SMEM_B>>>(
            Ah, Al, Wh, Wl, bih, xp, MD, Gq, inDim, 0, 0, 0);

        const float* Whh = l ? dWhh + (size_t)(l - 1) * Gq * Hq : dWhh0;
        lstm_persist<32><<<128, 256, smemDec>>>(
            xp, Whh, h0P + (size_t)l * Bq * Hq, c0P + (size_t)l * Bq * Hq,
            hA, hB, cst, Xcur, nullptr, nullptr,
            TDq, 0, 512, 0);

        Xin = Xcur; inDim = Hq;
        Xcur = (Xcur == X0) ? X1 : X0;
    }

    gemm128<<<dim3(Fq / 128, (Bq * TDq) / 128, 1), 256>>>(
        Xin, outW, outB, out, Bq * TDq, Fq, Hq, 0, 0, 0, 0, 0);
}

// round 6
// speedup vs baseline: 2.4600x; 1.7617x over previous
#include <cuda_runtime.h>
#include <cuda_bf16.h>
#include <math.h>
#include <stdint.h>

#define Bq 64
#define TSq 300
#define TDq 180
#define Fq 128
#define Hq 512
#define Lq 4
#define Gq 2048   // 4*H

// ---------------- static device scratch (no runtime allocation) ----------------
__device__ float g_xp[(size_t)2 * Bq * TSq * Gq];
__device__ float g_X0[(size_t)Bq * TSq * 1024];
__device__ float g_X1[(size_t)Bq * TSq * 1024];
__device__ float g_dcat[(size_t)Bq * TDq * 640];
__device__ float g_hwork[2][2 * Bq * Hq];
__device__ float g_cwork[2 * Bq * Hq];
__device__ float g_hs[Lq * Bq * 1024];
__device__ float g_cs[Lq * Bq * 1024];
__device__ float g_h0[Lq * Bq * Hq];
__device__ float g_c0[Lq * Bq * Hq];
__device__ unsigned g_barCnt;
__device__ unsigned g_barGen;
// bf16 split buffers for tensor-core projections
__device__ __nv_bfloat16 g_Ah[(size_t)Bq * TSq * 1024];
__device__ __nv_bfloat16 g_Al[(size_t)Bq * TSq * 1024];
__device__ __nv_bfloat16 g_Wh[(size_t)2 * Gq * 1024];
__device__ __nv_bfloat16 g_Wl[(size_t)2 * Gq * 1024];

// -------- packed f32x2 helpers (bridge/output GEMM) --------
#define FMA_F32X2(acc, a, b) \
    asm("fma.rn.f32x2 %0, %1, %2, %0;" : "+l"(acc) : "l"(a), "l"(b))
#define PACK_DUP(out, v) do { \
    unsigned _u = __float_as_uint(v); \
    asm("mov.b64 %0, {%1, %1};" : "=l"(out) : "r"(_u)); } while (0)
#define UNPACK_2(lo, hi, in) \
    asm("mov.b64 {%0, %1}, %2;" : "=r"(lo), "=r"(hi) : "l"(in))

// -------- mma.sync / ldmatrix / cp.async helpers (compute_103-safe) -----
__device__ __forceinline__ uint32_t smem_u32(const void* p) {
    uint32_t a;
    asm("{ .reg .u64 t; cvta.to.shared.u64 t, %1; cvt.u32.u64 %0, t; }" : "=r"(a) : "l"(p));
    return a;
}
#define LDM_X4(r0, r1, r2, r3, addr) \
    asm volatile("ldmatrix.sync.aligned.m8n8.x4.shared.b16 {%0,%1,%2,%3}, [%4];" \
        : "=r"(r0), "=r"(r1), "=r"(r2), "=r"(r3) : "r"(addr))
#define LDM_X2(r0, r1, addr) \
    asm volatile("ldmatrix.sync.aligned.m8n8.x2.shared.b16 {%0,%1}, [%2];" \
        : "=r"(r0), "=r"(r1) : "r"(addr))
#define MMA_BF16(c0, c1, c2, c3, a0, a1, a2, a3, b0, b1) \
    asm volatile("mma.sync.aligned.m16n8k16.row.col.f32.bf16.bf16.f32 " \
        "{%0,%1,%2,%3}, {%4,%5,%6,%7}, {%8,%9}, {%0,%1,%2,%3};" \
        : "+f"(c0), "+f"(c1), "+f"(c2), "+f"(c3) \
        : "r"(a0), "r"(a1), "r"(a2), "r"(a3), "r"(b0), "r"(b1))
#define CPA16(dst, src) \
    asm volatile("cp.async.cg.shared.global [%0], [%1], 16;" :: "r"(dst), "l"(src))
#define CPA_COMMIT() asm volatile("cp.async.commit_group;" ::: "memory")
#define CPA_WAIT(n)  asm volatile("cp.async.wait_group %0;" :: "n"(n) : "memory")

__device__ __forceinline__ uint32_t bf2pack(float fhi, float flo) {
    uint32_t r;
    asm("cvt.rn.bf16x2.f32 %0, %1, %2;" : "=r"(r) : "f"(fhi), "f"(flo));
    return r;
}
__device__ __forceinline__ float trunc_hi(float f) {
    return __uint_as_float(__float_as_uint(f) & 0xFFFF0000u);
}
// split 8 consecutive floats (two float4) into bf16 hi (trunc) and lo (residual)
__device__ __forceinline__ void split8(float4 a, float4 b, uint4& hi, uint4& lo) {
    hi.x = __byte_perm(__float_as_uint(a.x), __float_as_uint(a.y), 0x7632);
    hi.y = __byte_perm(__float_as_uint(a.z), __float_as_uint(a.w), 0x7632);
    hi.z = __byte_perm(__float_as_uint(b.x), __float_as_uint(b.y), 0x7632);
    hi.w = __byte_perm(__float_as_uint(b.z), __float_as_uint(b.w), 0x7632);
    lo.x = bf2pack(a.y - trunc_hi(a.y), a.x - trunc_hi(a.x));
    lo.y = bf2pack(a.w - trunc_hi(a.w), a.z - trunc_hi(a.z));
    lo.z = bf2pack(b.y - trunc_hi(b.y), b.x - trunc_hi(b.x));
    lo.w = bf2pack(b.w - trunc_hi(b.w), b.z - trunc_hi(b.z));
}

// ---------------------------------------------------------------------------
// software grid barrier (all blocks co-resident by construction: grid<=128)
// ---------------------------------------------------------------------------
__device__ __forceinline__ void gridBarrier()
{
    __syncthreads();
    if (threadIdx.x == 0) {
        const unsigned gen = *((volatile unsigned*)&g_barGen);
        __threadfence();
        if (atomicAdd(&g_barCnt, 1u) == gridDim.x - 1u) {
            atomicExch(&g_barCnt, 0u);
            __threadfence();
            atomicAdd(&g_barGen, 1u);
        } else {
            while (*((volatile unsigned*)&g_barGen) == gen) { __nanosleep(64); }
        }
        __threadfence();
    }
    __syncthreads();
}

// ---------------------------------------------------------------------------
// fp32 -> bf16 hi/lo split (elementwise), n % 4 == 0
// ---------------------------------------------------------------------------
__global__ void conv_split(const float* __restrict__ in, __nv_bfloat16* __restrict__ hi,
                           __nv_bfloat16* __restrict__ lo, size_t n)
{
    const size_t i = ((size_t)blockIdx.x * 256 + threadIdx.x) * 4;
    if (i >= n) return;
    const float4 v = *(const float4*)(in + i);
    __nv_bfloat16 h0 = __float2bfloat16(v.x), h1 = __float2bfloat16(v.y);
    __nv_bfloat16 h2 = __float2bfloat16(v.z), h3 = __float2bfloat16(v.w);
    __nv_bfloat16 l0 = __float2bfloat16(v.x - __bfloat162float(h0));
    __nv_bfloat16 l1 = __float2bfloat16(v.y - __bfloat162float(h1));
    __nv_bfloat16 l2 = __float2bfloat16(v.z - __bfloat162float(h2));
    __nv_bfloat16 l3 = __float2bfloat16(v.w - __bfloat162float(h3));
    __nv_bfloat162 hp0(h0, h1), hp1(h2, h3), lp0(l0, l1), lp1(l2, l3);
    *(uint2*)(hi + i) = make_uint2(*(uint32_t*)&hp0, *(uint32_t*)&hp1);
    *(uint2*)(lo + i) = make_uint2(*(uint32_t*)&lp0, *(uint32_t*)&lp1);
}

// ---------------------------------------------------------------------------
// Split-bf16 tensor-core GEMM via mma.sync (projections) — unchanged (round 5)
// ---------------------------------------------------------------------------
#define MMA_TILE_B   8192
#define MMA_BUF_B    (4 * MMA_TILE_B)
#define MMA_SMEM_B   (2 * MMA_BUF_B)

__global__ __launch_bounds__(256, 2)
void mma_xp(const __nv_bfloat16* __restrict__ Ah, const __nv_bfloat16* __restrict__ Al,
            const __nv_bfloat16* __restrict__ Wh, const __nv_bfloat16* __restrict__ Wl,
            const float* __restrict__ bias, float* __restrict__ C,
            int M, int N, int K, size_t wZ, size_t bZ, size_t cZ)
{
    extern __shared__ __align__(128) char smem[];
    const uint32_t sbase = smem_u32(smem);

    Wh   += blockIdx.z * wZ;
    Wl   += blockIdx.z * wZ;
    bias += blockIdx.z * bZ;
    C    += blockIdx.z * cZ;
    const int n0 = blockIdx.x * 128;
    const int m0 = blockIdx.y * 128;

    const int tid  = threadIdx.x;
    const int lane = tid & 31;
    const int warp = tid >> 5;
    const int wm = warp >> 2;
    const int wn = warp & 3;

    float acc[4][4][4];
#pragma unroll
    for (int i = 0; i < 4; i++)
#pragma unroll
        for (int j = 0; j < 4; j++)
#pragma unroll
            for (int q = 0; q < 4; q++) acc[i][j][q] = 0.f;

    const int gi0 = tid, gi1 = tid + 256;
    const int r0g = gi0 >> 2, g0 = gi0 & 3;
    const int r1g = gi1 >> 2, g1 = gi1 & 3;
    const uint32_t so0 = (uint32_t)(r0g * 64 + ((g0 ^ (r0g & 3)) << 4));
    const uint32_t so1 = (uint32_t)(r1g * 64 + ((g1 ^ (r1g & 3)) << 4));

    const int arow = wm * 64 + (lane & 15);
    const int aswz = arow & 3;
    const int agoff = lane >> 4;
    const int brow = wn * 32 + (lane & 7);
    const int bgoff = (lane >> 3) & 1;
    const int bnt   = (lane >> 4);

    const int nch = K >> 5;

    {
#pragma unroll
        for (int h = 0; h < 2; h++) {
            const int rr = h ? r1g : r0g;
            const int gg = h ? g1 : g0;
            const uint32_t so = h ? so1 : so0;
            const size_t ka = (size_t)gg * 8;
            CPA16(sbase + 0 * MMA_TILE_B + so, Ah + (size_t)(m0 + rr) * K + ka);
            CPA16(sbase + 1 * MMA_TILE_B + so, Al + (size_t)(m0 + rr) * K + ka);
            CPA16(sbase + 2 * MMA_TILE_B + so, Wh + (size_t)(n0 + rr) * K + ka);
            CPA16(sbase + 3 * MMA_TILE_B + so, Wl + (size_t)(n0 + rr) * K + ka);
        }
        CPA_COMMIT();
    }

    for (int c = 0; c < nch; c++) {
        const uint32_t buf = (uint32_t)(c & 1) * MMA_BUF_B;
        if (c + 1 < nch) {
            const uint32_t nbuf = (uint32_t)((c + 1) & 1) * MMA_BUF_B;
            const int k0 = (c + 1) << 5;
#pragma unroll
            for (int h = 0; h < 2; h++) {
                const int rr = h ? r1g : r0g;
                const int gg = h ? g1 : g0;
                const uint32_t so = h ? so1 : so0;
                const size_t ka = (size_t)k0 + gg * 8;
                CPA16(sbase + nbuf + 0 * MMA_TILE_B + so, Ah + (size_t)(m0 + rr) * K + ka);
                CPA16(sbase + nbuf + 1 * MMA_TILE_B + so, Al + (size_t)(m0 + rr) * K + ka);
                CPA16(sbase + nbuf + 2 * MMA_TILE_B + so, Wh + (size_t)(n0 + rr) * K + ka);
                CPA16(sbase + nbuf + 3 * MMA_TILE_B + so, Wl + (size_t)(n0 + rr) * K + ka);
            }
            CPA_COMMIT();
            CPA_WAIT(1);
        } else {
            CPA_WAIT(0);
        }
        __syncthreads();

        const uint32_t aH = sbase + buf + 0 * MMA_TILE_B;
        const uint32_t aL = sbase + buf + 1 * MMA_TILE_B;
        const uint32_t wH = sbase + buf + 2 * MMA_TILE_B;
        const uint32_t wL = sbase + buf + 3 * MMA_TILE_B;

#pragma unroll
        for (int ks = 0; ks < 2; ks++) {
            uint32_t af[4][4], bh[4][2], bl[4][2];
#pragma unroll
            for (int mt = 0; mt < 4; mt++) {
                const int rA = arow + mt * 16;
                const uint32_t ad = aH + (uint32_t)(rA * 64 + (((ks * 2 + agoff) ^ aswz) << 4));
                LDM_X4(af[mt][0], af[mt][1], af[mt][2], af[mt][3], ad);
            }
#pragma unroll
            for (int p = 0; p < 2; p++) {
                const int rB = brow + (p * 2 + bnt) * 8;
                const uint32_t off = (uint32_t)(rB * 64 + (((ks * 2 + bgoff) ^ (rB & 3)) << 4));
                LDM_X4(bh[p * 2][0], bh[p * 2][1], bh[p * 2 + 1][0], bh[p * 2 + 1][1], wH + off);
                LDM_X4(bl[p * 2][0], bl[p * 2][1], bl[p * 2 + 1][0], bl[p * 2 + 1][1], wL + off);
            }
#pragma unroll
            for (int mt = 0; mt < 4; mt++)
#pragma unroll
                for (int nt = 0; nt < 4; nt++) {
                    MMA_BF16(acc[mt][nt][0], acc[mt][nt][1], acc[mt][nt][2], acc[mt][nt][3],
                             af[mt][0], af[mt][1], af[mt][2], af[mt][3],
                             bh[nt][0], bh[nt][1]);
                    MMA_BF16(acc[mt][nt][0], acc[mt][nt][1], acc[mt][nt][2], acc[mt][nt][3],
                             af[mt][0], af[mt][1], af[mt][2], af[mt][3],
                             bl[nt][0], bl[nt][1]);
                }
#pragma unroll
            for (int mt = 0; mt < 4; mt++) {
                const int rA = arow + mt * 16;
                const uint32_t ad = aL + (uint32_t)(rA * 64 + (((ks * 2 + agoff) ^ aswz) << 4));
                LDM_X4(af[mt][0], af[mt][1], af[mt][2], af[mt][3], ad);
            }
#pragma unroll
            for (int mt = 0; mt < 4; mt++)
#pragma unroll
                for (int nt = 0; nt < 4; nt++)
                    MMA_BF16(acc[mt][nt][0], acc[mt][nt][1], acc[mt][nt][2], acc[mt][nt][3],
                             af[mt][0], af[mt][1], af[mt][2], af[mt][3],
                             bh[nt][0], bh[nt][1]);
        }
        __syncthreads();
    }

    const int mE = m0 + wm * 64 + (lane >> 2);
    const int nE = n0 + wn * 32 + (lane & 3) * 2;
#pragma unroll
    for (int mt = 0; mt < 4; mt++) {
#pragma unroll
        for (int nt = 0; nt < 4; nt++) {
            const int m = mE + mt * 16;
            const int n = nE + nt * 8;
            const float b0 = bias[n], b1 = bias[n + 1];
            float2 v0 = make_float2(acc[mt][nt][0] + b0, acc[mt][nt][1] + b1);
            float2 v1 = make_float2(acc[mt][nt][2] + b0, acc[mt][nt][3] + b1);
            *(float2*)(C + (size_t)m * N + n)       = v0;
            *(float2*)(C + (size_t)(m + 8) * N + n) = v1;
        }
    }
}

// ---------------------------------------------------------------------------
// fp32 f32x2 GEMM (small: bridges + output projection)
// ---------------------------------------------------------------------------
__global__ __launch_bounds__(256, 2)
void gemm128(const float* __restrict__ A, const float* __restrict__ W,
             const float* __restrict__ bias, float* __restrict__ C,
             int M, int N, int K,
             size_t aZ, size_t wZ, size_t bZ, size_t cZ, int act)
{
    A    += blockIdx.z * aZ;
    W    += blockIdx.z * wZ;
    bias += blockIdx.z * bZ;
    C    += blockIdx.z * cZ;
    const int n0 = blockIdx.x * 128;
    const int m0 = blockIdx.y * 128;

    __shared__ float As[8][128];
    __shared__ float Bs[8][128];

    const int tid = threadIdx.x;
    const int ty = tid >> 4, tx = tid & 15;
    const int lrow = tid >> 1;
    const int lq   = (tid & 1) * 4;

    unsigned long long accp[4][8];
#pragma unroll
    for (int i = 0; i < 4; i++)
#pragma unroll
        for (int j = 0; j < 8; j++) accp[i][j] = 0ull;

    for (int k0 = 0; k0 < K; k0 += 8) {
        float4 av = *(const float4*)(A + (size_t)(m0 + lrow) * K + k0 + lq);
        float4 wv = *(const float4*)(W + (size_t)(n0 + lrow) * K + k0 + lq);
        As[lq + 0][lrow] = av.x; As[lq + 1][lrow] = av.y;
        As[lq + 2][lrow] = av.z; As[lq + 3][lrow] = av.w;
        Bs[lq + 0][lrow] = wv.x; Bs[lq + 1][lrow] = wv.y;
        Bs[lq + 2][lrow] = wv.z; Bs[lq + 3][lrow] = wv.w;
        __syncthreads();
#pragma unroll
        for (int k = 0; k < 8; k++) {
            unsigned long long ap[4];
#pragma unroll
            for (int pi = 0; pi < 4; pi++)
                ap[pi] = *(const unsigned long long*)&As[k][ty * 8 + 2 * pi];
            const float4 b0 = *(const float4*)&Bs[k][tx * 8];
            const float4 b1 = *(const float4*)&Bs[k][tx * 8 + 4];
            unsigned long long bd[8];
            PACK_DUP(bd[0], b0.x); PACK_DUP(bd[1], b0.y);
            PACK_DUP(bd[2], b0.z); PACK_DUP(bd[3], b0.w);
            PACK_DUP(bd[4], b1.x); PACK_DUP(bd[5], b1.y);
            PACK_DUP(bd[6], b1.z); PACK_DUP(bd[7], b1.w);
#pragma unroll
            for (int pi = 0; pi < 4; pi++)
#pragma unroll
                for (int j = 0; j < 8; j++)
                    FMA_F32X2(accp[pi][j], ap[pi], bd[j]);
        }
        __syncthreads();
    }

#pragma unroll
    for (int pi = 0; pi < 4; pi++) {
        const size_t mA = (size_t)(m0 + ty * 8 + 2 * pi);
#pragma unroll
        for (int j = 0; j < 8; j++) {
            const int n = n0 + tx * 8 + j;
            unsigned lo, hi;
            UNPACK_2(lo, hi, accp[pi][j]);
            float vlo = __uint_as_float(lo) + bias[n];
            float vhi = __uint_as_float(hi) + bias[n];
            if (act) { vlo = tanhf(vlo); vhi = tanhf(vhi); }
            C[mA * N + n]       = vlo;
            C[(mA + 1) * N + n] = vhi;
        }
    }
}

// ---------------------------------------------------------------------------
// Persistent LSTM layer with tensor-core recurrence.
// NBL = gate columns per block (32: encoder 2dirs x 64 blocks; 16: decoder
// 128 blocks). Block computes gates[64 x NBL] = h[64x512] @ WhhT via split-bf16
// mma.sync (3 terms). Whh resident in smem as bf16 hi/lo (converted once).
// Per step: convert h (fp32, ldcg) -> smem bf16 hi/lo, mma, +xp, cell update.
// smem: Ah[64x1024B] Al[64x1024B] Bh[NBLx1024B] Bl[NBLx1024B] Gs[64][NBL+2]
// ---------------------------------------------------------------------------
template<int NBL>
__global__ __launch_bounds__(256)
void lstm_persist(const float* __restrict__ xp, const float* __restrict__ Whh,
                  const float* __restrict__ h0, const float* __restrict__ c0,
                  float* __restrict__ hA, float* __restrict__ hB,
                  float* __restrict__ cSt, float* __restrict__ y,
                  float* __restrict__ hFin, float* __restrict__ cFin,
                  int T, int revDir1, int yStride, int yDirMult)
{
    constexpr int U    = NBL / 4;          // units per block
    constexpr int USH  = (NBL == 32) ? 3 : 2;
    constexpr int WNT  = NBL / 16;         // n8 tiles per warp (2 or 1)
    constexpr int GSs  = NBL + 2;
    constexpr uint32_t S_AH = 0;
    constexpr uint32_t S_AL = 64 * 1024;
    constexpr uint32_t S_BH = 128 * 1024;
    constexpr uint32_t S_BL = S_BH + NBL * 1024;
    constexpr uint32_t S_GS = S_BL + NBL * 1024;

    extern __shared__ __align__(128) char smem[];
    const uint32_t sb = smem_u32(smem);
    float* Gs = (float*)(smem + S_GS);

    const int tid  = threadIdx.x;
    const int lane = tid & 31;
    const int warp = tid >> 5;
    const int mi = warp >> 1;              // m16 tile (batch block)
    const int nh = warp & 1;               // n-half

    int dir, u0;
    if (NBL == 32) { dir = blockIdx.x >> 6; u0 = (blockIdx.x & 63) * 8; }
    else           { dir = 0;               u0 = blockIdx.x * 4; }

    const float* xpd = xp  + (size_t)dir * Bq * T * Gq;
    const float* Wd  = Whh + (size_t)dir * Gq * Hq;
    float* hArr[2] = { hA + dir * Bq * Hq, hB + dir * Bq * Hq };
    float* cD = cSt + dir * Bq * Hq;

    // ---- convert Whh rows (gate-gathered) into smem bf16 hi/lo, swizzled ----
    for (int i = tid; i < NBL * 64; i += 256) {
        const int row = i >> 6;            // tile row = gc = gate*U + uu
        const int g   = i & 63;            // 16B granule along k
        const int gate = row >> (USH - 1) >> 1;   // row / U
        const int uu   = row & (U - 1);
        const int wrow = (gate << 9) + u0 + uu;
        const float4 va = *(const float4*)(Wd + (size_t)wrow * Hq + g * 8);
        const float4 vb = *(const float4*)(Wd + (size_t)wrow * Hq + g * 8 + 4);
        uint4 hi, lo;
        split8(va, vb, hi, lo);
        const uint32_t so = (uint32_t)(row * 1024 + ((g ^ (row & 7)) << 4));
        *(uint4*)(smem + S_BH + so) = hi;
        *(uint4*)(smem + S_BL + so) = lo;
    }

    // ---- init h, c for owned (batch x unit) slice ----
    for (int i = tid; i < Bq * U; i += 256) {
        const int b = i >> USH, uu = i & (U - 1), u = u0 + uu;
        hArr[0][b * Hq + u] = h0 ? h0[b * Hq + u] : 0.f;
        cD        [b * Hq + u] = c0 ? c0[b * Hq + u] : 0.f;
    }
    gridBarrier();

    // ldmatrix address components
    const int rowA = (lane & 15);          // + mi*16
    const int agoff = lane >> 4;
    const int bnt   = lane >> 4;
    const int bgoff = (lane >> 3) & 1;

    int ping = 0;
    for (int t = 0; t < T; t++) {
        const int tt = (dir == 1 && revDir1) ? (T - 1 - t) : t;
        const float* hI = hArr[ping];
        float*       hO = hArr[ping ^ 1];

        // ---- convert h -> smem bf16 hi/lo (64 rows x 64 granules) ----
#pragma unroll
        for (int it = 0; it < 16; it++) {
            const int slot = tid + it * 256;
            const int row = slot >> 6, g = slot & 63;
            const float4 va = __ldcg((const float4*)(hI + (size_t)row * Hq + g * 8));
            const float4 vb = __ldcg((const float4*)(hI + (size_t)row * Hq + g * 8 + 4));
            uint4 hi, lo;
            split8(va, vb, hi, lo);
            const uint32_t so = (uint32_t)(row * 1024 + ((g ^ (row & 7)) << 4));
            *(uint4*)(smem + S_AH + so) = hi;
            *(uint4*)(smem + S_AL + so) = lo;
        }
        __syncthreads();

        // ---- mma: gates[64 x NBL] ----
        float acc[WNT][4];
#pragma unroll
        for (int nt = 0; nt < WNT; nt++)
#pragma unroll
            for (int q = 0; q < 4; q++) acc[nt][q] = 0.f;

#pragma unroll 4
        for (int ks = 0; ks < 32; ks++) {
            const int rA = mi * 16 + rowA;
            const uint32_t aoff = (uint32_t)(rA * 1024 + (((ks * 2 + agoff) ^ (rA & 7)) << 4));
            uint32_t ah[4], al[4], bh[2 * WNT], bl[2 * WNT];
            LDM_X4(ah[0], ah[1], ah[2], ah[3], sb + S_AH + aoff);
            LDM_X4(al[0], al[1], al[2], al[3], sb + S_AL + aoff);
            if (WNT == 2) {
                const int rB = nh * 16 + bnt * 8 + (lane & 7);
                const uint32_t boff = (uint32_t)(rB * 1024 + (((ks * 2 + bgoff) ^ (rB & 7)) << 4));
                LDM_X4(bh[0], bh[1], bh[2], bh[3], sb + S_BH + boff);
                LDM_X4(bl[0], bl[1], bl[2], bl[3], sb + S_BL + boff);
            } else {
                const int rB = nh * 8 + (lane & 7);
                const uint32_t boff = (uint32_t)(rB * 1024 + (((ks * 2 + bgoff) ^ (rB & 7)) << 4));
                LDM_X2(bh[0], bh[1], sb + S_BH + boff);
                LDM_X2(bl[0], bl[1], sb + S_BL + boff);
            }
#pragma unroll
            for (int nt = 0; nt < WNT; nt++) {
                MMA_BF16(acc[nt][0], acc[nt][1], acc[nt][2], acc[nt][3],
                         ah[0], ah[1], ah[2], ah[3], bh[nt * 2], bh[nt * 2 + 1]);
                MMA_BF16(acc[nt][0], acc[nt][1], acc[nt][2], acc[nt][3],
                         ah[0], ah[1], ah[2], ah[3], bl[nt * 2], bl[nt * 2 + 1]);
                MMA_BF16(acc[nt][0], acc[nt][1], acc[nt][2], acc[nt][3],
                         al[0], al[1], al[2], al[3], bh[nt * 2], bh[nt * 2 + 1]);
            }
        }

        // ---- write gate sums to Gs ----
        {
            const int gr  = lane >> 2;
            const int gcq = (lane & 3) * 2;
            const int m = mi * 16 + gr;
#pragma unroll
            for (int nt = 0; nt < WNT; nt++) {
                const int gc = nh * (WNT * 8) + nt * 8 + gcq;
                *(float2*)&Gs[m * GSs + gc]       = make_float2(acc[nt][0], acc[nt][1]);
                *(float2*)&Gs[(m + 8) * GSs + gc] = make_float2(acc[nt][2], acc[nt][3]);
            }
        }
        __syncthreads();

        // ---- cell update (+ xp add) ----
#pragma unroll
        for (int i = tid; i < Bq * U; i += 256) {
            const int b = i >> USH, uu = i & (U - 1);
            const int u = u0 + uu;
            const size_t xb = ((size_t)b * T + tt) * Gq + u;
            const float iv = Gs[b * GSs + 0 * U + uu] + xpd[xb];
            const float fv = Gs[b * GSs + 1 * U + uu] + xpd[xb + 512];
            const float gv = Gs[b * GSs + 2 * U + uu] + xpd[xb + 1024];
            const float ov = Gs[b * GSs + 3 * U + uu] + xpd[xb + 1536];
            const float cOld = cD[b * Hq + u];
            const float si = 1.f / (1.f + expf(-iv));
            const float sf = 1.f / (1.f + expf(-fv));
            const float so = 1.f / (1.f + expf(-ov));
            const float cN = sf * cOld + si * tanhf(gv);
            const float hN = so * tanhf(cN);
            cD[b * Hq + u] = cN;
            hO[b * Hq + u] = hN;
            y[((size_t)b * T + tt) * yStride + dir * yDirMult + u] = hN;
        }

        gridBarrier();
        ping ^= 1;
    }

    if (hFin) {
        for (int i = tid; i < Bq * U; i += 256) {
            const int b = i >> USH, uu = i & (U - 1), u = u0 + uu;
            hFin[b * 1024 + dir * 512 + u] = hArr[ping][b * Hq + u];
            cFin[b * 1024 + dir * 512 + u] = cD[b * Hq + u];
        }
    }
}

#define SMEM_ENC (128 * 1024 + 2 * 32 * 1024 + 64 * 34 * 4)
#define SMEM_DEC (128 * 1024 + 2 * 16 * 1024 + 64 * 18 * 4)

// decoder input: concat(tgt_in, sc_emb[scenario[b]])
__global__ void build_dcat(const float* __restrict__ tgt, const float* __restrict__ scEmb,
                           const int* __restrict__ scen, float* __restrict__ out)
{
    const size_t i = (size_t)blockIdx.x * 256 + threadIdx.x;
    if (i >= (size_t)Bq * TDq * 640) return;
    const int r = (int)(i / 640);
    const int j = (int)(i - (size_t)r * 640);
    float v;
    if (j < 128) v = tgt[(size_t)r * 128 + j];
    else         v = scEmb[scen[r / TDq] * 512 + (j - 128)];
    out[i] = v;
}

// ---------------------------------------------------------------------------
extern "C" void kernel_launch(void* const* d_in, const int* in_sizes, int n_in,
                              void* d_out, int out_size)
{
    (void)in_sizes; (void)n_in; (void)out_size;
    const float* src   = (const float*)d_in[0];
    const float* tgt   = (const float*)d_in[1];
    const int*   scen  = (const int*)  d_in[2];
    const float* eWih0 = (const float*)d_in[3];
    const float* eWhh0 = (const float*)d_in[4];
    const float* eB0   = (const float*)d_in[5];
    const float* eWih  = (const float*)d_in[6];
    const float* eWhh  = (const float*)d_in[7];
    const float* eB    = (const float*)d_in[8];
    const float* hbW   = (const float*)d_in[9];
    const float* hbB   = (const float*)d_in[10];
    const float* cbW   = (const float*)d_in[11];
    const float* cbB   = (const float*)d_in[12];
    const float* scEmb = (const float*)d_in[13];
    const float* dWih0 = (const float*)d_in[14];
    const float* dWhh0 = (const float*)d_in[15];
    const float* dB0   = (const float*)d_in[16];
    const float* dWih  = (const float*)d_in[17];
    const float* dWhh  = (const float*)d_in[18];
    const float* dB    = (const float*)d_in[19];
    const float* outW  = (const float*)d_in[20];
    const float* outB  = (const float*)d_in[21];
    float* out = (float*)d_out;

    float *xp, *X0, *X1, *dcat, *hwork, *cst, *hsP, *csP, *h0P, *c0P;
    __nv_bfloat16 *Ah, *Al, *Wh, *Wl;
    cudaGetSymbolAddress((void**)&xp,    g_xp);
    cudaGetSymbolAddress((void**)&X0,    g_X0);
    cudaGetSymbolAddress((void**)&X1,    g_X1);
    cudaGetSymbolAddress((void**)&dcat,  g_dcat);
    cudaGetSymbolAddress((void**)&hwork, g_hwork);
    cudaGetSymbolAddress((void**)&cst,   g_cwork);
    cudaGetSymbolAddress((void**)&hsP,   g_hs);
    cudaGetSymbolAddress((void**)&csP,   g_cs);
    cudaGetSymbolAddress((void**)&h0P,   g_h0);
    cudaGetSymbolAddress((void**)&c0P,   g_c0);
    cudaGetSymbolAddress((void**)&Ah,    g_Ah);
    cudaGetSymbolAddress((void**)&Al,    g_Al);
    cudaGetSymbolAddress((void**)&Wh,    g_Wh);
    cudaGetSymbolAddress((void**)&Wl,    g_Wl);
    float* hA = hwork;
    float* hB = hwork + 2 * Bq * Hq;

    cudaFuncSetAttribute(lstm_persist<32>, cudaFuncAttributeMaxDynamicSharedMemorySize, SMEM_ENC);
    cudaFuncSetAttribute(lstm_persist<16>, cudaFuncAttributeMaxDynamicSharedMemorySize, SMEM_DEC);
    cudaFuncSetAttribute(mma_xp, cudaFuncAttributeMaxDynamicSharedMemorySize, MMA_SMEM_B);

    const int ME = Bq * TSq;   // 19200
    const int MD = Bq * TDq;   // 11520

    // ======================= encoder =======================
    const float* Xin = src;
    int inDim = Fq;
    float* Xcur = X0;
    for (int l = 0; l < Lq; l++) {
        const float* Wih = l ? eWih + (size_t)(l - 1) * 2 * Gq * 1024 : eWih0;
        const float* bih = l ? eB   + (size_t)(l - 1) * 2 * Gq        : eB0;

        const size_t nA = (size_t)ME * inDim;
        const size_t nW = (size_t)2 * Gq * inDim;
        conv_split<<<(int)((nA / 4 + 255) / 256), 256>>>(Xin, Ah, Al, nA);
        conv_split<<<(int)((nW / 4 + 255) / 256), 256>>>(Wih, Wh, Wl, nW);
        mma_xp<<<dim3(Gq / 128, ME / 128, 2), 256, MMA_SMEM_B>>>(
            Ah, Al, Wh, Wl, bih, xp, ME, Gq, inDim,
            (size_t)Gq * inDim, (size_t)Gq, (size_t)ME * Gq);

        const float* Whh = l ? eWhh + (size_t)(l - 1) * 2 * Gq * Hq : eWhh0;
        lstm_persist<32><<<128, 256, SMEM_ENC>>>(
            xp, Whh, nullptr, nullptr, hA, hB, cst, Xcur,
            hsP + (size_t)l * Bq * 1024, csP + (size_t)l * Bq * 1024,
            TSq, 1, 1024, 512);

        Xin = Xcur; inDim = 1024;
        Xcur = (Xcur == X0) ? X1 : X0;
    }

    // ======================= bridges (tanh GEMMs, fp32) =======================
    gemm128<<<dim3(Hq / 128, (Lq * Bq) / 128, 1), 256>>>(
        hsP, hbW, hbB, h0P, Lq * Bq, Hq, 1024, 0, 0, 0, 0, 1);
    gemm128<<<dim3(Hq / 128, (Lq * Bq) / 128, 1), 256>>>(
        csP, cbW, cbB, c0P, Lq * Bq, Hq, 1024, 0, 0, 0, 0, 1);

    // ======================= decoder =======================
    build_dcat<<<(int)(((size_t)Bq * TDq * 640 + 255) / 256), 256>>>(tgt, scEmb, scen, dcat);

    Xin = dcat; inDim = Fq + Hq;
    for (int l = 0; l < Lq; l++) {
        const float* Wih = l ? dWih + (size_t)(l - 1) * Gq * Hq : dWih0;
        const float* bih = l ? dB   + (size_t)(l - 1) * Gq      : dB0;

        const size_t nA = (size_t)MD * inDim;
        const size_t nW = (size_t)Gq * inDim;
        conv_split<<<(int)((nA / 4 + 255) / 256), 256>>>(Xin, Ah, Al, nA);
        conv_split<<<(int)((nW / 4 + 255) / 256), 256>>>(Wih, Wh, Wl, nW);
        mma_xp<<<dim3(Gq / 128, MD / 128, 1), 256, MMA_SMEM_B>>>(
            Ah, Al, Wh, Wl, bih, xp, MD, Gq, inDim, 0, 0, 0);

        const float* Whh = l ? dWhh + (size_t)(l - 1) * Gq * Hq : dWhh0;
        lstm_persist<16><<<128, 256, SMEM_DEC>>>(
            xp, Whh, h0P + (size_t)l * Bq * Hq, c0P + (size_t)l * Bq * Hq,
            hA, hB, cst, Xcur, nullptr, nullptr,
            TDq, 0, 512, 0);

        Xin = Xcur; inDim = Hq;
        Xcur = (Xcur == X0) ? X1 : X0;
    }

    gemm128<<<dim3(Fq / 128, (Bq * TDq) / 128, 1), 256>>>(
        Xin, outW, outB, out, Bq * TDq, Fq, Hq, 0, 0, 0, 0, 0);
}